// round 2
// baseline (speedup 1.0000x reference)
#include <cuda_runtime.h>
#include <cstdint>

// Problem dims (fixed by the reference)
#define BB   64
#define NSET 512
#define DIN  512
#define DH   1024
#define MPHI (BB * NSET)   // 32768

// Scratch (device globals: the sanctioned no-alloc workaround)
__device__ float g_h1[(size_t)MPHI * DH];     // 128 MB: relu(x@W1+b1)
__device__ float g_pooled[BB * 2 * DH];       // [64, 2048]: [sum | max]
__device__ float g_r1[BB * DH];               // [64, 1024]

// ---------------------------------------------------------------------------
// Zero the pooled buffer (needed every launch; atomics accumulate into it)
// ---------------------------------------------------------------------------
__global__ void init_pooled_kernel() {
    int i = blockIdx.x * blockDim.x + threadIdx.x;
    if (i < BB * 2 * DH) g_pooled[i] = 0.0f;
}

// ---------------------------------------------------------------------------
// SGEMM: C[M,N] = relu(A[M,K] @ W[K,N] + bias[N])
// BM=BN=128, BK=16, 256 threads, 8x8 per-thread tile.
// MODE 0: A = param, store to g_h1.
// MODE 1: A = g_h1, fused sum/max pooling into g_pooled (no C store).
// All dims assumed divisible by tiles (they are: 32768, 512/1024, 1024).
// ---------------------------------------------------------------------------
template <int MODE>
__global__ void __launch_bounds__(256)
sgemm_bias_relu(const float* __restrict__ Ain,
                const float* __restrict__ W,
                const float* __restrict__ bias,
                int M, int K, int N)
{
    const int BM = 128, BN = 128, BK = 16;
    __shared__ float As[BK][BM + 4];   // transposed A tile, padded
    __shared__ float Bs[BK][BN];
    __shared__ float red[16][128];     // pooling reduction (MODE 1)

    const float* A = (MODE == 1) ? (const float*)g_h1 : Ain;

    const int tid    = threadIdx.x;
    const int ty     = tid >> 4;          // 0..15
    const int tx     = tid & 15;          // 0..15
    const int rowOff = ty << 3;           // 0..120
    const int colOff = tx << 3;           // 0..120
    const int rowBlk = blockIdx.y * BM;
    const int colBlk = blockIdx.x * BN;

    float c[8][8];
#pragma unroll
    for (int i = 0; i < 8; i++)
#pragma unroll
        for (int j = 0; j < 8; j++) c[i][j] = 0.0f;

    for (int kt = 0; kt < K; kt += BK) {
        // --- load A tile (128 rows x 16 k), transposed into As ---
#pragma unroll
        for (int l = 0; l < 2; l++) {
            int f   = tid + l * 256;          // float4 id 0..511
            int row = f >> 2;                 // 0..127
            int kq  = f & 3;                  // 0..3
            float4 v = *reinterpret_cast<const float4*>(
                &A[(size_t)(rowBlk + row) * K + kt + (kq << 2)]);
            As[kq * 4 + 0][row] = v.x;
            As[kq * 4 + 1][row] = v.y;
            As[kq * 4 + 2][row] = v.z;
            As[kq * 4 + 3][row] = v.w;
        }
        // --- load B tile (16 k x 128 cols) ---
#pragma unroll
        for (int l = 0; l < 2; l++) {
            int f  = tid + l * 256;           // float4 id 0..511
            int kb = f >> 5;                  // 0..15
            int cq = f & 31;                  // 0..31
            *reinterpret_cast<float4*>(&Bs[kb][cq << 2]) =
                *reinterpret_cast<const float4*>(
                    &W[(size_t)(kt + kb) * N + colBlk + (cq << 2)]);
        }
        __syncthreads();

#pragma unroll
        for (int kk = 0; kk < BK; kk++) {
            float a_frag[8], b_frag[8];
            *reinterpret_cast<float4*>(&a_frag[0]) =
                *reinterpret_cast<const float4*>(&As[kk][rowOff]);
            *reinterpret_cast<float4*>(&a_frag[4]) =
                *reinterpret_cast<const float4*>(&As[kk][rowOff + 4]);
            *reinterpret_cast<float4*>(&b_frag[0]) =
                *reinterpret_cast<const float4*>(&Bs[kk][colOff]);
            *reinterpret_cast<float4*>(&b_frag[4]) =
                *reinterpret_cast<const float4*>(&Bs[kk][colOff + 4]);
#pragma unroll
            for (int i = 0; i < 8; i++)
#pragma unroll
                for (int j = 0; j < 8; j++)
                    c[i][j] += a_frag[i] * b_frag[j];
        }
        __syncthreads();
    }

    // bias
    float bb[8];
#pragma unroll
    for (int j = 0; j < 8; j++) bb[j] = bias[colBlk + colOff + j];

    if (MODE == 0) {
        // relu + store to g_h1
#pragma unroll
        for (int i = 0; i < 8; i++) {
            size_t base = (size_t)(rowBlk + rowOff + i) * N + colBlk + colOff;
            float4 v0, v1;
            v0.x = fmaxf(c[i][0] + bb[0], 0.f);
            v0.y = fmaxf(c[i][1] + bb[1], 0.f);
            v0.z = fmaxf(c[i][2] + bb[2], 0.f);
            v0.w = fmaxf(c[i][3] + bb[3], 0.f);
            v1.x = fmaxf(c[i][4] + bb[4], 0.f);
            v1.y = fmaxf(c[i][5] + bb[5], 0.f);
            v1.z = fmaxf(c[i][6] + bb[6], 0.f);
            v1.w = fmaxf(c[i][7] + bb[7], 0.f);
            *reinterpret_cast<float4*>(&g_h1[base])     = v0;
            *reinterpret_cast<float4*>(&g_h1[base + 4]) = v1;
        }
    } else {
        // relu + fused sum/max pooling over rows (set dim).
        // Tile rows all lie inside one batch (128 | 512).
        const int bIdx = rowBlk >> 9;   // rowBlk / 512

        float s[8], mx[8];
#pragma unroll
        for (int j = 0; j < 8; j++) { s[j] = 0.f; mx[j] = 0.f; }
#pragma unroll
        for (int i = 0; i < 8; i++)
#pragma unroll
            for (int j = 0; j < 8; j++) {
                float v = fmaxf(c[i][j] + bb[j], 0.f);
                s[j]  += v;
                mx[j]  = fmaxf(mx[j], v);
            }

        // sum reduce across the 16 thread-rows, then one atomic per column
#pragma unroll
        for (int j = 0; j < 8; j++) red[ty][colOff + j] = s[j];
        __syncthreads();
        if (ty == 0) {
#pragma unroll
            for (int j = 0; j < 8; j++) {
                float t = 0.f;
#pragma unroll
                for (int r = 0; r < 16; r++) t += red[r][colOff + j];
                atomicAdd(&g_pooled[bIdx * (2 * DH) + colBlk + colOff + j], t);
            }
        }
        __syncthreads();
        // max reduce (relu output >= 0, so int-bit compare is order-preserving
        // and the 0-initialized buffer is the correct identity)
#pragma unroll
        for (int j = 0; j < 8; j++) red[ty][colOff + j] = mx[j];
        __syncthreads();
        if (ty == 0) {
#pragma unroll
            for (int j = 0; j < 8; j++) {
                float m = red[0][colOff + j];
#pragma unroll
                for (int r = 1; r < 16; r++) m = fmaxf(m, red[r][colOff + j]);
                atomicMax(reinterpret_cast<int*>(
                              &g_pooled[bIdx * (2 * DH) + DH + colBlk + colOff + j]),
                          __float_as_int(m));
            }
        }
    }
}

// ---------------------------------------------------------------------------
// Small rho GEMM: out[64,1024] = relu(A[64,K] @ W[K,1024] + bias)
// PHASE 0: A = g_pooled (K=2048), out = g_r1
// PHASE 1: A = g_r1    (K=1024), out = param (final output)
// One block per 32 columns; block = 8 row-threads x 32 col-threads,
// each thread accumulates 8 rows so each W element is read once & reused 8x.
// ---------------------------------------------------------------------------
template <int PHASE>
__global__ void __launch_bounds__(256)
rho_gemm(const float* __restrict__ W,
         const float* __restrict__ bias,
         float* __restrict__ outp)
{
    const int K = (PHASE == 0) ? (2 * DH) : DH;
    const int N = DH;
    const float* A = (PHASE == 0) ? (const float*)g_pooled : (const float*)g_r1;
    float* out     = (PHASE == 0) ? (float*)g_r1 : outp;

    __shared__ float As[64][65];   // padded

    const int tx  = threadIdx.x & 31;   // col within block tile
    const int ty  = threadIdx.x >> 5;   // 0..7 (row group)
    const int col = blockIdx.x * 32 + tx;

    float acc[8];
#pragma unroll
    for (int r = 0; r < 8; r++) acc[r] = 0.f;

    for (int kt = 0; kt < K; kt += 64) {
        // load A tile [64 rows x 64 k]
#pragma unroll
        for (int l = 0; l < 4; l++) {
            int f   = threadIdx.x + l * 256;  // float4 id 0..1023
            int row = f >> 4;                 // 0..63
            int kq  = f & 15;                 // 0..15
            float4 v = *reinterpret_cast<const float4*>(
                &A[(size_t)row * K + kt + (kq << 2)]);
            As[row][kq * 4 + 0] = v.x;
            As[row][kq * 4 + 1] = v.y;
            As[row][kq * 4 + 2] = v.z;
            As[row][kq * 4 + 3] = v.w;
        }
        __syncthreads();

#pragma unroll
        for (int kk = 0; kk < 64; kk++) {
            float w = W[(size_t)(kt + kk) * N + col];
#pragma unroll
            for (int r = 0; r < 8; r++)
                acc[r] += As[ty * 8 + r][kk] * w;
        }
        __syncthreads();
    }

    float bv = bias[col];
#pragma unroll
    for (int r = 0; r < 8; r++)
        out[(size_t)(ty * 8 + r) * N + col] = fmaxf(acc[r] + bv, 0.f);
}

// ---------------------------------------------------------------------------
// Launch
// ---------------------------------------------------------------------------
extern "C" void kernel_launch(void* const* d_in, const int* in_sizes, int n_in,
                              void* d_out, int out_size)
{
    const float* x    = (const float*)d_in[0];   // [64, 512, 512]
    const float* W1   = (const float*)d_in[1];   // [512, 1024]
    const float* b1   = (const float*)d_in[2];   // [1024]
    const float* W2   = (const float*)d_in[3];   // [1024, 1024]
    const float* b2   = (const float*)d_in[4];   // [1024]
    const float* Wr1  = (const float*)d_in[5];   // [2048, 1024]
    const float* br1  = (const float*)d_in[6];   // [1024]
    const float* Wr2  = (const float*)d_in[7];   // [1024, 1024]
    const float* br2  = (const float*)d_in[8];   // [1024]
    float* out        = (float*)d_out;           // [64, 1024]

    // zero pooled accumulator
    init_pooled_kernel<<<(BB * 2 * DH + 255) / 256, 256>>>();

    // phi layer 1: g_h1 = relu(x @ W1 + b1)
    {
        dim3 grid(DH / 128, MPHI / 128);   // (8, 256)
        sgemm_bias_relu<0><<<grid, 256>>>(x, W1, b1, MPHI, DIN, DH);
    }
    // phi layer 2 + fused pooling: g_pooled = [sum | max] over set dim
    {
        dim3 grid(DH / 128, MPHI / 128);   // (8, 256)
        sgemm_bias_relu<1><<<grid, 256>>>(nullptr, W2, b2, MPHI, DH, DH);
    }
    // rho layer 1: g_r1 = relu(g_pooled @ Wr1 + br1)
    rho_gemm<0><<<DH / 32, 256>>>(Wr1, br1, nullptr);
    // rho layer 2: out = relu(g_r1 @ Wr2 + br2)
    rho_gemm<1><<<DH / 32, 256>>>(Wr2, br2, out);
}

// round 4
// speedup vs baseline: 2.4507x; 2.4507x over previous
#include <cuda_runtime.h>
#include <cuda_bf16.h>
#include <cstdint>

// ---------------------------------------------------------------------------
// Problem dims
// ---------------------------------------------------------------------------
#define BB   64
#define NSET 512
#define DIN  512
#define DH   1024
#define MPHI (BB * NSET)   // 32768

// GEMM tiling
#define BM 128
#define BN 128
#define BK 64                      // bf16 elements per K chunk (128B rows)
#define OFF_AH 0
#define OFF_AL 16384
#define OFF_BH 32768
#define OFF_BL 49152
#define STAGE  65536
#define DYN_SMEM (2 * STAGE + 1024)

// ---------------------------------------------------------------------------
// Device scratch (globals = sanctioned no-alloc workaround)
// ---------------------------------------------------------------------------
__device__ unsigned short g_x_hi[(size_t)MPHI * DIN];
__device__ unsigned short g_x_lo[(size_t)MPHI * DIN];
__device__ unsigned short g_w1t_hi[(size_t)DH * DIN];    // [N, K]
__device__ unsigned short g_w1t_lo[(size_t)DH * DIN];
__device__ unsigned short g_w2t_hi[(size_t)DH * DH];
__device__ unsigned short g_w2t_lo[(size_t)DH * DH];
__device__ unsigned short g_h1_hi[(size_t)MPHI * DH];
__device__ unsigned short g_h1_lo[(size_t)MPHI * DH];
__device__ float g_pooled[BB * 2 * DH];
__device__ float g_racc1[BB * DH];
__device__ float g_racc2[BB * DH];
__device__ float g_r1[BB * DH];

// ---------------------------------------------------------------------------
// PTX helpers (sm_80-class only: cp.async, ldmatrix, mma.sync)
// ---------------------------------------------------------------------------
__device__ __forceinline__ uint32_t smem_u32(const void* p) {
    uint32_t a;
    asm("{ .reg .u64 t; cvta.to.shared.u64 t, %1; cvt.u32.u64 %0, t; }"
        : "=r"(a) : "l"(p));
    return a;
}

__device__ __forceinline__ void cp16(uint32_t dst, const void* src) {
    asm volatile("cp.async.cg.shared.global [%0], [%1], 16;"
                 :: "r"(dst), "l"(src));
}
#define CP_COMMIT() asm volatile("cp.async.commit_group;" ::: "memory")
#define CP_WAIT(n)  asm volatile("cp.async.wait_group %0;" :: "n"(n) : "memory")

__device__ __forceinline__ void ldsm_x4(uint32_t& r0, uint32_t& r1,
                                        uint32_t& r2, uint32_t& r3, uint32_t addr) {
    asm volatile("ldmatrix.sync.aligned.m8n8.x4.shared.b16 {%0,%1,%2,%3}, [%4];"
                 : "=r"(r0), "=r"(r1), "=r"(r2), "=r"(r3) : "r"(addr));
}

__device__ __forceinline__ void mma16816(float* c, const uint32_t* a, const uint32_t* b) {
    asm volatile(
        "mma.sync.aligned.m16n8k16.row.col.f32.bf16.bf16.f32 "
        "{%0,%1,%2,%3}, {%4,%5,%6,%7}, {%8,%9}, {%0,%1,%2,%3};"
        : "+f"(c[0]), "+f"(c[1]), "+f"(c[2]), "+f"(c[3])
        : "r"(a[0]), "r"(a[1]), "r"(a[2]), "r"(a[3]), "r"(b[0]), "r"(b[1]));
}

__device__ __forceinline__ void split_store(unsigned short* dhi, unsigned short* dlo,
                                            size_t idx, float v0, float v1) {
    __nv_bfloat16 h0 = __float2bfloat16(v0);
    __nv_bfloat16 h1 = __float2bfloat16(v1);
    __nv_bfloat16 l0 = __float2bfloat16(v0 - __bfloat162float(h0));
    __nv_bfloat16 l1 = __float2bfloat16(v1 - __bfloat162float(h1));
    *(uint32_t*)&dhi[idx] = ((uint32_t)__bfloat16_as_ushort(h1) << 16)
                          | (uint32_t)__bfloat16_as_ushort(h0);
    *(uint32_t*)&dlo[idx] = ((uint32_t)__bfloat16_as_ushort(l1) << 16)
                          | (uint32_t)__bfloat16_as_ushort(l0);
}

// ---------------------------------------------------------------------------
// HMMA 3xBF16 GEMM.  MODE 0: layer1 (x @ W1 -> h1 split).
//                    MODE 1: layer2 (h1 @ W2 -> fused sum/max pooling).
// CTA 128x128, BK=64, 2-stage cp.async, 8 warps (2m x 4n), warp tile 64x32.
// ---------------------------------------------------------------------------
template <int MODE>
__global__ void __launch_bounds__(256, 1)
phi_gemm(const float* __restrict__ bias, int K, int C)
{
    extern __shared__ char dsm[];
    __shared__ float sbias[BN];
    __shared__ float sSum[2][128], sMax[2][128];

    const int tid  = threadIdx.x;
    const int lane = tid & 31;
    const int wid  = tid >> 5;
    const int wm   = wid >> 2;     // 0..1
    const int wn   = wid & 3;      // 0..3
    const int rowBlk = blockIdx.y * BM;
    const int colBlk = blockIdx.x * BN;

    const unsigned short* Ahi = (MODE == 0) ? g_x_hi  : g_h1_hi;
    const unsigned short* Alo = (MODE == 0) ? g_x_lo  : g_h1_lo;
    const unsigned short* Bhi = (MODE == 0) ? g_w1t_hi : g_w2t_hi;
    const unsigned short* Blo = (MODE == 0) ? g_w1t_lo : g_w2t_lo;

    const uint32_t sb = (smem_u32(dsm) + 1023u) & ~1023u;

    if (tid < BN) sbias[tid] = bias[colBlk + tid];

    float acc[4][4][4];
#pragma unroll
    for (int i = 0; i < 4; i++)
#pragma unroll
        for (int j = 0; j < 4; j++)
#pragma unroll
            for (int k = 0; k < 4; k++) acc[i][j][k] = 0.f;

    // per-thread ldmatrix base offsets (swizzle applied to chunk-byte only)
    const int arow = wm * 64 + (lane & 15);
    const uint32_t aRowOff = (uint32_t)arow * 128;
    const uint32_t aXor = ((uint32_t)(arow & 7)) << 4;
    const int brow = wn * 32 + (lane & 15);
    const uint32_t bRowOff = (uint32_t)brow * 128;
    const uint32_t bXor = ((uint32_t)(brow & 7)) << 4;
    const uint32_t csel = ((uint32_t)((lane >> 4) & 1)) << 4;

    // stage loader: A tile 128x64 + B tile 128x64, hi & lo (4 x 16KB)
    auto load_chunk = [&](int stage, int kt) {
        uint32_t st = sb + stage * STAGE;
#pragma unroll
        for (int l = 0; l < 4; l++) {
            int f = tid + l * 256;            // 0..1023
            int r = f >> 3, q = f & 7;
            uint32_t off = (uint32_t)(r * 128) +
                           (((uint32_t)(q * 16)) ^ (((uint32_t)(r & 7)) << 4));
            size_t ga = (size_t)(rowBlk + r) * K + kt + q * 8;
            size_t gb = (size_t)(colBlk + r) * K + kt + q * 8;
            cp16(st + OFF_AH + off, Ahi + ga);
            cp16(st + OFF_AL + off, Alo + ga);
            cp16(st + OFF_BH + off, Bhi + gb);
            cp16(st + OFF_BL + off, Blo + gb);
        }
        CP_COMMIT();
    };

    load_chunk(0, 0);
    load_chunk(1, BK);

    for (int c = 0; c < C; c++) {
        if (c + 1 < C) { CP_WAIT(1); } else { CP_WAIT(0); }
        __syncthreads();

        const uint32_t st = sb + (c & 1) * STAGE;
#pragma unroll
        for (int k16 = 0; k16 < 4; k16++) {
            const uint32_t cb = k16 * 32;
            uint32_t ah[4][4], al[4][4], bh[4][2], bl[4][2];
#pragma unroll
            for (int mi = 0; mi < 4; mi++) {
                uint32_t aoff = aRowOff + mi * 2048 + ((cb + csel) ^ aXor);
                ldsm_x4(ah[mi][0], ah[mi][1], ah[mi][2], ah[mi][3], st + OFF_AH + aoff);
                ldsm_x4(al[mi][0], al[mi][1], al[mi][2], al[mi][3], st + OFF_AL + aoff);
            }
#pragma unroll
            for (int nb = 0; nb < 2; nb++) {
                uint32_t boff = bRowOff + nb * 2048 + ((cb + csel) ^ bXor);
                uint32_t r0, r1, r2, r3;
                ldsm_x4(r0, r1, r2, r3, st + OFF_BH + boff);
                bh[nb * 2][0] = r0; bh[nb * 2][1] = r2;
                bh[nb * 2 + 1][0] = r1; bh[nb * 2 + 1][1] = r3;
                ldsm_x4(r0, r1, r2, r3, st + OFF_BL + boff);
                bl[nb * 2][0] = r0; bl[nb * 2][1] = r2;
                bl[nb * 2 + 1][0] = r1; bl[nb * 2 + 1][1] = r3;
            }
#pragma unroll
            for (int mi = 0; mi < 4; mi++)
#pragma unroll
                for (int ni = 0; ni < 4; ni++) {
                    mma16816(acc[mi][ni], ah[mi], bh[ni]);   // hi*hi
                    mma16816(acc[mi][ni], ah[mi], bl[ni]);   // hi*lo
                    mma16816(acc[mi][ni], al[mi], bh[ni]);   // lo*hi
                }
        }
        __syncthreads();
        if (c + 2 < C) load_chunk(c & 1, (c + 2) * BK);
    }

    // ------------------------- epilogue -------------------------
    const int r0base = wm * 64 + (lane >> 2);
    const int n0base = wn * 32 + 2 * (lane & 3);

    if (MODE == 0) {
#pragma unroll
        for (int mi = 0; mi < 4; mi++) {
            int r0 = rowBlk + r0base + mi * 16;
#pragma unroll
            for (int ni = 0; ni < 4; ni++) {
                int nrel = n0base + ni * 8;
                float b0 = sbias[nrel], b1 = sbias[nrel + 1];
                float v00 = fmaxf(acc[mi][ni][0] + b0, 0.f);
                float v01 = fmaxf(acc[mi][ni][1] + b1, 0.f);
                float v10 = fmaxf(acc[mi][ni][2] + b0, 0.f);
                float v11 = fmaxf(acc[mi][ni][3] + b1, 0.f);
                size_t base0 = (size_t)r0 * DH + colBlk + nrel;
                size_t base1 = (size_t)(r0 + 8) * DH + colBlk + nrel;
                split_store(g_h1_hi, g_h1_lo, base0, v00, v01);
                split_store(g_h1_hi, g_h1_lo, base1, v10, v11);
            }
        }
    } else {
        const int bIdx = rowBlk >> 9;   // 512 rows per batch, 128 | 512
        float s[4][2], mx[4][2];
#pragma unroll
        for (int ni = 0; ni < 4; ni++) { s[ni][0] = s[ni][1] = 0.f;
                                         mx[ni][0] = mx[ni][1] = 0.f; }
#pragma unroll
        for (int mi = 0; mi < 4; mi++)
#pragma unroll
            for (int ni = 0; ni < 4; ni++) {
                int nrel = n0base + ni * 8;
                float b0 = sbias[nrel], b1 = sbias[nrel + 1];
                float v00 = fmaxf(acc[mi][ni][0] + b0, 0.f);
                float v01 = fmaxf(acc[mi][ni][1] + b1, 0.f);
                float v10 = fmaxf(acc[mi][ni][2] + b0, 0.f);
                float v11 = fmaxf(acc[mi][ni][3] + b1, 0.f);
                s[ni][0] += v00 + v10;  s[ni][1] += v01 + v11;
                mx[ni][0] = fmaxf(mx[ni][0], fmaxf(v00, v10));
                mx[ni][1] = fmaxf(mx[ni][1], fmaxf(v01, v11));
            }
        // reduce over the 8 lane-rows (lanes sharing lane&3)
#pragma unroll
        for (int o = 4; o < 32; o <<= 1)
#pragma unroll
            for (int ni = 0; ni < 4; ni++)
#pragma unroll
                for (int j = 0; j < 2; j++) {
                    s[ni][j]  += __shfl_xor_sync(0xffffffffu, s[ni][j], o);
                    mx[ni][j]  = fmaxf(mx[ni][j],
                                       __shfl_xor_sync(0xffffffffu, mx[ni][j], o));
                }
        if ((lane >> 2) == 0) {
#pragma unroll
            for (int ni = 0; ni < 4; ni++)
#pragma unroll
                for (int j = 0; j < 2; j++) {
                    int col = wn * 32 + ni * 8 + 2 * lane + j;
                    sSum[wm][col] = s[ni][j];
                    sMax[wm][col] = mx[ni][j];
                }
        }
        __syncthreads();
        if (tid < 128) {
            float S = sSum[0][tid] + sSum[1][tid];
            float M = fmaxf(sMax[0][tid], sMax[1][tid]);
            atomicAdd(&g_pooled[bIdx * 2 * DH + colBlk + tid], S);
            atomicMax((int*)&g_pooled[bIdx * 2 * DH + DH + colBlk + tid],
                      __float_as_int(M));
        }
    }
}

// ---------------------------------------------------------------------------
// Prep kernels
// ---------------------------------------------------------------------------
__global__ void zero_init_kernel() {
    int i = blockIdx.x * 256 + threadIdx.x;
    if (i < BB * 2 * DH) g_pooled[i] = 0.f;
    if (i < BB * DH) { g_racc1[i] = 0.f; g_racc2[i] = 0.f; }
}

__global__ void split_x_kernel(const float* __restrict__ src, int n2) {
    int i = blockIdx.x * 256 + threadIdx.x;
    if (i >= n2) return;
    float2 v = ((const float2*)src)[i];
    __nv_bfloat16 h0 = __float2bfloat16(v.x);
    __nv_bfloat16 h1 = __float2bfloat16(v.y);
    __nv_bfloat16 l0 = __float2bfloat16(v.x - __bfloat162float(h0));
    __nv_bfloat16 l1 = __float2bfloat16(v.y - __bfloat162float(h1));
    ((uint32_t*)g_x_hi)[i] = ((uint32_t)__bfloat16_as_ushort(h1) << 16)
                           | (uint32_t)__bfloat16_as_ushort(h0);
    ((uint32_t*)g_x_lo)[i] = ((uint32_t)__bfloat16_as_ushort(l1) << 16)
                           | (uint32_t)__bfloat16_as_ushort(l0);
}

// src [R, Cn] fp32 -> dst [Cn, R] bf16 hi/lo
template <int WSEL>
__global__ void transpose_split_kernel(const float* __restrict__ src, int R, int Cn) {
    __shared__ float t[32][33];
    unsigned short* dhi = (WSEL == 0) ? g_w1t_hi : g_w2t_hi;
    unsigned short* dlo = (WSEL == 0) ? g_w1t_lo : g_w2t_lo;
    int bx = blockIdx.x * 32, by = blockIdx.y * 32;
    int tx = threadIdx.x, ty = threadIdx.y;
#pragma unroll
    for (int i = 0; i < 32; i += 8)
        t[ty + i][tx] = src[(size_t)(by + ty + i) * Cn + bx + tx];
    __syncthreads();
#pragma unroll
    for (int i = 0; i < 32; i += 8) {
        float v = t[tx][ty + i];
        int n = bx + ty + i, k = by + tx;
        __nv_bfloat16 h = __float2bfloat16(v);
        dhi[(size_t)n * R + k] = __bfloat16_as_ushort(h);
        dlo[(size_t)n * R + k] = __bfloat16_as_ushort(
            __float2bfloat16(v - __bfloat162float(h)));
    }
}

// ---------------------------------------------------------------------------
// rho GEMMs: split-K FFMA with atomic fp32 accumulation.
// ---------------------------------------------------------------------------
template <int PHASE>
__global__ void __launch_bounds__(256)
rho_partial(const float* __restrict__ W)
{
    const int lda = (PHASE == 0) ? 2 * DH : DH;
    const float* A = (PHASE == 0) ? (const float*)g_pooled : (const float*)g_r1;
    float* acc     = (PHASE == 0) ? g_racc1 : g_racc2;

    __shared__ float As[64][65];
    const int tid = threadIdx.x;
    const int tx = tid & 31, ty = tid >> 5;
    const int col = blockIdx.x * 32 + tx;
    const int k0 = blockIdx.y * 256;

    float a8[8];
#pragma unroll
    for (int r = 0; r < 8; r++) a8[r] = 0.f;

    for (int kt = k0; kt < k0 + 256; kt += 64) {
#pragma unroll
        for (int l = 0; l < 4; l++) {
            int f = tid + l * 256;
            int row = f >> 4, q = f & 15;
            float4 v = *reinterpret_cast<const float4*>(
                &A[(size_t)row * lda + kt + q * 4]);
            As[row][q * 4 + 0] = v.x; As[row][q * 4 + 1] = v.y;
            As[row][q * 4 + 2] = v.z; As[row][q * 4 + 3] = v.w;
        }
        __syncthreads();
#pragma unroll
        for (int kk = 0; kk < 64; kk++) {
            float w = W[(size_t)(kt + kk) * DH + col];
#pragma unroll
            for (int r = 0; r < 8; r++) a8[r] += As[ty * 8 + r][kk] * w;
        }
        __syncthreads();
    }
#pragma unroll
    for (int r = 0; r < 8; r++)
        atomicAdd(&acc[(size_t)(ty * 8 + r) * DH + col], a8[r]);
}

template <int PHASE>
__global__ void bias_relu_kernel(const float* __restrict__ b, float* __restrict__ outp) {
    int i = blockIdx.x * 256 + threadIdx.x;
    const float* acc = (PHASE == 0) ? g_racc1 : g_racc2;
    float* out = (PHASE == 0) ? g_r1 : outp;
    out[i] = fmaxf(acc[i] + b[i & (DH - 1)], 0.f);
}

// ---------------------------------------------------------------------------
// Launch
// ---------------------------------------------------------------------------
extern "C" void kernel_launch(void* const* d_in, const int* in_sizes, int n_in,
                              void* d_out, int out_size)
{
    const float* x   = (const float*)d_in[0];
    const float* W1  = (const float*)d_in[1];
    const float* b1  = (const float*)d_in[2];
    const float* W2  = (const float*)d_in[3];
    const float* b2  = (const float*)d_in[4];
    const float* Wr1 = (const float*)d_in[5];
    const float* br1 = (const float*)d_in[6];
    const float* Wr2 = (const float*)d_in[7];
    const float* br2 = (const float*)d_in[8];
    float* out       = (float*)d_out;

    cudaFuncSetAttribute(phi_gemm<0>, cudaFuncAttributeMaxDynamicSharedMemorySize, DYN_SMEM);
    cudaFuncSetAttribute(phi_gemm<1>, cudaFuncAttributeMaxDynamicSharedMemorySize, DYN_SMEM);

    // prep
    zero_init_kernel<<<512, 256>>>();
    split_x_kernel<<<(MPHI * DIN / 2 + 255) / 256, 256>>>(x, MPHI * DIN / 2);
    transpose_split_kernel<0><<<dim3(DH / 32, DIN / 32), dim3(32, 8)>>>(W1, DIN, DH);
    transpose_split_kernel<1><<<dim3(DH / 32, DH / 32),  dim3(32, 8)>>>(W2, DH, DH);

    // phi layer 1: h1 = relu(x @ W1 + b1), split to bf16 hi/lo
    phi_gemm<0><<<dim3(DH / BN, MPHI / BM), 256, DYN_SMEM>>>(b1, DIN, DIN / BK);
    // phi layer 2 + fused sum/max pooling
    phi_gemm<1><<<dim3(DH / BN, MPHI / BM), 256, DYN_SMEM>>>(b2, DH, DH / BK);

    // rho
    rho_partial<0><<<dim3(DH / 32, 8), 256>>>(Wr1);   // K=2048, 8 splits
    bias_relu_kernel<0><<<BB * DH / 256, 256>>>(br1, nullptr);
    rho_partial<1><<<dim3(DH / 32, 4), 256>>>(Wr2);   // K=1024, 4 splits
    bias_relu_kernel<1><<<BB * DH / 256, 256>>>(br2, out);
}

// round 5
// speedup vs baseline: 2.5559x; 1.0429x over previous
#include <cuda_runtime.h>
#include <cuda_bf16.h>
#include <cstdint>

// ---------------------------------------------------------------------------
// Problem dims
// ---------------------------------------------------------------------------
#define BB   64
#define NSET 512
#define DIN  512
#define DH   1024
#define MPHI (BB * NSET)   // 32768

// GEMM tiling: CTA 128x256, BK=64, warp tile 64x64 (2x4 warps)
#define BM 128
#define BN 256
#define BK 64
#define OFF_AH 0
#define OFF_AL 16384
#define OFF_BH 32768
#define OFF_BL 98304      // 32768 + 65536
#define STAGE  163840     // 16K+16K+64K+64K = 160KB? -> no: A 16K*2 + B 32K*2 = 96KB
// A: 128 rows * 128B = 16KB each (hi, lo). B: 256 rows * 128B = 32KB each.
#undef OFF_BL
#undef STAGE
#define OFF_BL 65536      // AH 0..16K, AL 16K..32K, BH 32K..64K, BL 64K..96K
#define STAGE  98304
#define DYN_SMEM (2 * STAGE + 1024)

// ---------------------------------------------------------------------------
// Device scratch
// ---------------------------------------------------------------------------
__device__ unsigned short g_x_hi[(size_t)MPHI * DIN];
__device__ unsigned short g_x_lo[(size_t)MPHI * DIN];
__device__ unsigned short g_w1t_hi[(size_t)DH * DIN];    // [N, K]
__device__ unsigned short g_w1t_lo[(size_t)DH * DIN];
__device__ unsigned short g_w2t_hi[(size_t)DH * DH];
__device__ unsigned short g_w2t_lo[(size_t)DH * DH];
__device__ unsigned short g_h1_hi[(size_t)MPHI * DH];
__device__ unsigned short g_h1_lo[(size_t)MPHI * DH];
__device__ float g_pooled[BB * 2 * DH];
__device__ float g_racc1[BB * DH];
__device__ float g_racc2[BB * DH];
__device__ float g_r1[BB * DH];

// ---------------------------------------------------------------------------
// PTX helpers (sm_80-class only)
// ---------------------------------------------------------------------------
__device__ __forceinline__ uint32_t smem_u32(const void* p) {
    uint32_t a;
    asm("{ .reg .u64 t; cvta.to.shared.u64 t, %1; cvt.u32.u64 %0, t; }"
        : "=r"(a) : "l"(p));
    return a;
}

__device__ __forceinline__ void cp16(uint32_t dst, const void* src) {
    asm volatile("cp.async.cg.shared.global [%0], [%1], 16;"
                 :: "r"(dst), "l"(src));
}
#define CP_COMMIT() asm volatile("cp.async.commit_group;" ::: "memory")
#define CP_WAIT(n)  asm volatile("cp.async.wait_group %0;" :: "n"(n) : "memory")

__device__ __forceinline__ void ldsm_x4(uint32_t& r0, uint32_t& r1,
                                        uint32_t& r2, uint32_t& r3, uint32_t addr) {
    asm volatile("ldmatrix.sync.aligned.m8n8.x4.shared.b16 {%0,%1,%2,%3}, [%4];"
                 : "=r"(r0), "=r"(r1), "=r"(r2), "=r"(r3) : "r"(addr));
}

__device__ __forceinline__ void mma16816(float* c, const uint32_t* a, const uint32_t* b) {
    asm volatile(
        "mma.sync.aligned.m16n8k16.row.col.f32.bf16.bf16.f32 "
        "{%0,%1,%2,%3}, {%4,%5,%6,%7}, {%8,%9}, {%0,%1,%2,%3};"
        : "+f"(c[0]), "+f"(c[1]), "+f"(c[2]), "+f"(c[3])
        : "r"(a[0]), "r"(a[1]), "r"(a[2]), "r"(a[3]), "r"(b[0]), "r"(b[1]));
}

__device__ __forceinline__ void split_store(unsigned short* dhi, unsigned short* dlo,
                                            size_t idx, float v0, float v1) {
    __nv_bfloat16 h0 = __float2bfloat16(v0);
    __nv_bfloat16 h1 = __float2bfloat16(v1);
    __nv_bfloat16 l0 = __float2bfloat16(v0 - __bfloat162float(h0));
    __nv_bfloat16 l1 = __float2bfloat16(v1 - __bfloat162float(h1));
    *(uint32_t*)&dhi[idx] = ((uint32_t)__bfloat16_as_ushort(h1) << 16)
                          | (uint32_t)__bfloat16_as_ushort(h0);
    *(uint32_t*)&dlo[idx] = ((uint32_t)__bfloat16_as_ushort(l1) << 16)
                          | (uint32_t)__bfloat16_as_ushort(l0);
}

// ---------------------------------------------------------------------------
// HMMA 3xBF16 GEMM.  MODE 0: layer1 (x @ W1 -> h1 split).
//                    MODE 1: layer2 (h1 @ W2 -> fused sum/max pooling).
// CTA 128x256, BK=64, 2-stage cp.async, 8 warps (2m x 4n), warp tile 64x64.
// ---------------------------------------------------------------------------
template <int MODE>
__global__ void __launch_bounds__(256, 1)
phi_gemm(const float* __restrict__ bias, int K, int C)
{
    extern __shared__ char dsm[];
    __shared__ float sbias[BN];
    __shared__ float sSum[2][BN], sMax[2][BN];

    const int tid  = threadIdx.x;
    const int lane = tid & 31;
    const int wid  = tid >> 5;
    const int wm   = wid >> 2;     // 0..1
    const int wn   = wid & 3;      // 0..3
    const int rowBlk = blockIdx.y * BM;
    const int colBlk = blockIdx.x * BN;

    const unsigned short* Ahi = (MODE == 0) ? g_x_hi  : g_h1_hi;
    const unsigned short* Alo = (MODE == 0) ? g_x_lo  : g_h1_lo;
    const unsigned short* Bhi = (MODE == 0) ? g_w1t_hi : g_w2t_hi;
    const unsigned short* Blo = (MODE == 0) ? g_w1t_lo : g_w2t_lo;

    const uint32_t sb = (smem_u32(dsm) + 1023u) & ~1023u;

    if (tid < BN) sbias[tid] = bias[colBlk + tid];

    float acc[4][8][4];
#pragma unroll
    for (int i = 0; i < 4; i++)
#pragma unroll
        for (int j = 0; j < 8; j++)
#pragma unroll
            for (int k = 0; k < 4; k++) acc[i][j][k] = 0.f;

    // ldmatrix per-thread addressing (swizzled 128B rows)
    const int arow = wm * 64 + (lane & 15);
    const uint32_t aRowOff = (uint32_t)arow * 128;
    const uint32_t aXor = ((uint32_t)(arow & 7)) << 4;
    const int brow = wn * 64 + (lane & 15);
    const uint32_t bRowOff = (uint32_t)brow * 128;
    const uint32_t bXor = ((uint32_t)(brow & 7)) << 4;
    const uint32_t csel = ((uint32_t)((lane >> 4) & 1)) << 4;

    // stage loader: A 128x64 hi/lo (16KB each) + B 256x64 hi/lo (32KB each)
    auto load_chunk = [&](int stage, int kt) {
        uint32_t st = sb + stage * STAGE;
#pragma unroll
        for (int l = 0; l < 4; l++) {               // A: 1024 cp16 per matrix
            int f = tid + l * 256;
            int r = f >> 3, q = f & 7;
            uint32_t off = (uint32_t)(r * 128) +
                           (((uint32_t)(q * 16)) ^ (((uint32_t)(r & 7)) << 4));
            size_t ga = (size_t)(rowBlk + r) * K + kt + q * 8;
            cp16(st + OFF_AH + off, Ahi + ga);
            cp16(st + OFF_AL + off, Alo + ga);
        }
#pragma unroll
        for (int l = 0; l < 8; l++) {               // B: 2048 cp16 per matrix
            int f = tid + l * 256;
            int r = f >> 3, q = f & 7;
            uint32_t off = (uint32_t)(r * 128) +
                           (((uint32_t)(q * 16)) ^ (((uint32_t)(r & 7)) << 4));
            size_t gb = (size_t)(colBlk + r) * K + kt + q * 8;
            cp16(st + OFF_BH + off, Bhi + gb);
            cp16(st + OFF_BL + off, Blo + gb);
        }
        CP_COMMIT();
    };

    load_chunk(0, 0);
    load_chunk(1, BK);

    for (int c = 0; c < C; c++) {
        if (c + 1 < C) { CP_WAIT(1); } else { CP_WAIT(0); }
        __syncthreads();

        const uint32_t st = sb + (c & 1) * STAGE;
#pragma unroll
        for (int k16 = 0; k16 < 4; k16++) {
            const uint32_t cb = k16 * 32;
            uint32_t ah[4][4], al[4][4], bh[8][2], bl[8][2];
#pragma unroll
            for (int mi = 0; mi < 4; mi++) {
                uint32_t aoff = aRowOff + mi * 2048 + ((cb + csel) ^ aXor);
                ldsm_x4(ah[mi][0], ah[mi][1], ah[mi][2], ah[mi][3], st + OFF_AH + aoff);
                ldsm_x4(al[mi][0], al[mi][1], al[mi][2], al[mi][3], st + OFF_AL + aoff);
            }
#pragma unroll
            for (int nb = 0; nb < 4; nb++) {
                uint32_t boff = bRowOff + nb * 2048 + ((cb + csel) ^ bXor);
                uint32_t r0, r1, r2, r3;
                ldsm_x4(r0, r1, r2, r3, st + OFF_BH + boff);
                bh[nb * 2][0] = r0; bh[nb * 2][1] = r2;
                bh[nb * 2 + 1][0] = r1; bh[nb * 2 + 1][1] = r3;
                ldsm_x4(r0, r1, r2, r3, st + OFF_BL + boff);
                bl[nb * 2][0] = r0; bl[nb * 2][1] = r2;
                bl[nb * 2 + 1][0] = r1; bl[nb * 2 + 1][1] = r3;
            }
#pragma unroll
            for (int mi = 0; mi < 4; mi++)
#pragma unroll
                for (int ni = 0; ni < 8; ni++) {
                    mma16816(acc[mi][ni], ah[mi], bh[ni]);   // hi*hi
                    mma16816(acc[mi][ni], ah[mi], bl[ni]);   // hi*lo
                    mma16816(acc[mi][ni], al[mi], bh[ni]);   // lo*hi
                }
        }
        __syncthreads();
        if (c + 2 < C) load_chunk(c & 1, (c + 2) * BK);
    }

    // ------------------------- epilogue -------------------------
    const int r0base = wm * 64 + (lane >> 2);
    const int n0base = wn * 64 + 2 * (lane & 3);

    if (MODE == 0) {
#pragma unroll
        for (int mi = 0; mi < 4; mi++) {
            int r0 = rowBlk + r0base + mi * 16;
#pragma unroll
            for (int ni = 0; ni < 8; ni++) {
                int nrel = n0base + ni * 8;
                float b0 = sbias[nrel], b1 = sbias[nrel + 1];
                float v00 = fmaxf(acc[mi][ni][0] + b0, 0.f);
                float v01 = fmaxf(acc[mi][ni][1] + b1, 0.f);
                float v10 = fmaxf(acc[mi][ni][2] + b0, 0.f);
                float v11 = fmaxf(acc[mi][ni][3] + b1, 0.f);
                size_t base0 = (size_t)r0 * DH + colBlk + nrel;
                size_t base1 = (size_t)(r0 + 8) * DH + colBlk + nrel;
                split_store(g_h1_hi, g_h1_lo, base0, v00, v01);
                split_store(g_h1_hi, g_h1_lo, base1, v10, v11);
            }
        }
    } else {
        const int bIdx = rowBlk >> 9;   // 512 rows per batch, 128 | 512
        float s[8][2], mx[8][2];
#pragma unroll
        for (int ni = 0; ni < 8; ni++) { s[ni][0] = s[ni][1] = 0.f;
                                         mx[ni][0] = mx[ni][1] = 0.f; }
#pragma unroll
        for (int mi = 0; mi < 4; mi++)
#pragma unroll
            for (int ni = 0; ni < 8; ni++) {
                int nrel = n0base + ni * 8;
                float b0 = sbias[nrel], b1 = sbias[nrel + 1];
                float v00 = fmaxf(acc[mi][ni][0] + b0, 0.f);
                float v01 = fmaxf(acc[mi][ni][1] + b1, 0.f);
                float v10 = fmaxf(acc[mi][ni][2] + b0, 0.f);
                float v11 = fmaxf(acc[mi][ni][3] + b1, 0.f);
                s[ni][0] += v00 + v10;  s[ni][1] += v01 + v11;
                mx[ni][0] = fmaxf(mx[ni][0], fmaxf(v00, v10));
                mx[ni][1] = fmaxf(mx[ni][1], fmaxf(v01, v11));
            }
        // reduce across the 8 lane-row groups
#pragma unroll
        for (int o = 4; o < 32; o <<= 1)
#pragma unroll
            for (int ni = 0; ni < 8; ni++)
#pragma unroll
                for (int j = 0; j < 2; j++) {
                    s[ni][j]  += __shfl_xor_sync(0xffffffffu, s[ni][j], o);
                    mx[ni][j]  = fmaxf(mx[ni][j],
                                       __shfl_xor_sync(0xffffffffu, mx[ni][j], o));
                }
        if ((lane >> 2) == 0) {
#pragma unroll
            for (int ni = 0; ni < 8; ni++)
#pragma unroll
                for (int j = 0; j < 2; j++) {
                    int col = wn * 64 + ni * 8 + 2 * lane + j;
                    sSum[wm][col] = s[ni][j];
                    sMax[wm][col] = mx[ni][j];
                }
        }
        __syncthreads();
        {
            float S = sSum[0][tid] + sSum[1][tid];
            float M = fmaxf(sMax[0][tid], sMax[1][tid]);
            atomicAdd(&g_pooled[bIdx * 2 * DH + colBlk + tid], S);
            atomicMax((int*)&g_pooled[bIdx * 2 * DH + DH + colBlk + tid],
                      __float_as_int(M));
        }
    }
}

// ---------------------------------------------------------------------------
// Prep kernels
// ---------------------------------------------------------------------------
__global__ void zero_init_kernel() {
    int i = blockIdx.x * 256 + threadIdx.x;
    if (i < BB * 2 * DH) g_pooled[i] = 0.f;
    if (i < BB * DH) { g_racc1[i] = 0.f; g_racc2[i] = 0.f; }
}

__global__ void split_x_kernel(const float* __restrict__ src, int n2) {
    int i = blockIdx.x * 256 + threadIdx.x;
    if (i >= n2) return;
    float2 v = ((const float2*)src)[i];
    __nv_bfloat16 h0 = __float2bfloat16(v.x);
    __nv_bfloat16 h1 = __float2bfloat16(v.y);
    __nv_bfloat16 l0 = __float2bfloat16(v.x - __bfloat162float(h0));
    __nv_bfloat16 l1 = __float2bfloat16(v.y - __bfloat162float(h1));
    ((uint32_t*)g_x_hi)[i] = ((uint32_t)__bfloat16_as_ushort(h1) << 16)
                           | (uint32_t)__bfloat16_as_ushort(h0);
    ((uint32_t*)g_x_lo)[i] = ((uint32_t)__bfloat16_as_ushort(l1) << 16)
                           | (uint32_t)__bfloat16_as_ushort(l0);
}

// src [R, Cn] fp32 -> dst [Cn, R] bf16 hi/lo
template <int WSEL>
__global__ void transpose_split_kernel(const float* __restrict__ src, int R, int Cn) {
    __shared__ float t[32][33];
    unsigned short* dhi = (WSEL == 0) ? g_w1t_hi : g_w2t_hi;
    unsigned short* dlo = (WSEL == 0) ? g_w1t_lo : g_w2t_lo;
    int bx = blockIdx.x * 32, by = blockIdx.y * 32;
    int tx = threadIdx.x, ty = threadIdx.y;
#pragma unroll
    for (int i = 0; i < 32; i += 8)
        t[ty + i][tx] = src[(size_t)(by + ty + i) * Cn + bx + tx];
    __syncthreads();
#pragma unroll
    for (int i = 0; i < 32; i += 8) {
        float v = t[tx][ty + i];
        int n = bx + ty + i, k = by + tx;
        __nv_bfloat16 h = __float2bfloat16(v);
        dhi[(size_t)n * R + k] = __bfloat16_as_ushort(h);
        dlo[(size_t)n * R + k] = __bfloat16_as_ushort(
            __float2bfloat16(v - __bfloat162float(h)));
    }
}

// ---------------------------------------------------------------------------
// rho GEMMs: split-K FFMA with atomic fp32 accumulation.
// ---------------------------------------------------------------------------
template <int PHASE>
__global__ void __launch_bounds__(256)
rho_partial(const float* __restrict__ W)
{
    const int lda = (PHASE == 0) ? 2 * DH : DH;
    const float* A = (PHASE == 0) ? (const float*)g_pooled : (const float*)g_r1;
    float* acc     = (PHASE == 0) ? g_racc1 : g_racc2;

    __shared__ float As[64][65];
    const int tid = threadIdx.x;
    const int tx = tid & 31, ty = tid >> 5;
    const int col = blockIdx.x * 32 + tx;
    const int k0 = blockIdx.y * 256;

    float a8[8];
#pragma unroll
    for (int r = 0; r < 8; r++) a8[r] = 0.f;

    for (int kt = k0; kt < k0 + 256; kt += 64) {
#pragma unroll
        for (int l = 0; l < 4; l++) {
            int f = tid + l * 256;
            int row = f >> 4, q = f & 15;
            float4 v = *reinterpret_cast<const float4*>(
                &A[(size_t)row * lda + kt + q * 4]);
            As[row][q * 4 + 0] = v.x; As[row][q * 4 + 1] = v.y;
            As[row][q * 4 + 2] = v.z; As[row][q * 4 + 3] = v.w;
        }
        __syncthreads();
#pragma unroll
        for (int kk = 0; kk < 64; kk++) {
            float w = W[(size_t)(kt + kk) * DH + col];
#pragma unroll
            for (int r = 0; r < 8; r++) a8[r] += As[ty * 8 + r][kk] * w;
        }
        __syncthreads();
    }
#pragma unroll
    for (int r = 0; r < 8; r++)
        atomicAdd(&acc[(size_t)(ty * 8 + r) * DH + col], a8[r]);
}

template <int PHASE>
__global__ void bias_relu_kernel(const float* __restrict__ b, float* __restrict__ outp) {
    int i = blockIdx.x * 256 + threadIdx.x;
    const float* acc = (PHASE == 0) ? g_racc1 : g_racc2;
    float* out = (PHASE == 0) ? g_r1 : outp;
    out[i] = fmaxf(acc[i] + b[i & (DH - 1)], 0.f);
}

// ---------------------------------------------------------------------------
// Launch
// ---------------------------------------------------------------------------
extern "C" void kernel_launch(void* const* d_in, const int* in_sizes, int n_in,
                              void* d_out, int out_size)
{
    const float* x   = (const float*)d_in[0];
    const float* W1  = (const float*)d_in[1];
    const float* b1  = (const float*)d_in[2];
    const float* W2  = (const float*)d_in[3];
    const float* b2  = (const float*)d_in[4];
    const float* Wr1 = (const float*)d_in[5];
    const float* br1 = (const float*)d_in[6];
    const float* Wr2 = (const float*)d_in[7];
    const float* br2 = (const float*)d_in[8];
    float* out       = (float*)d_out;

    cudaFuncSetAttribute(phi_gemm<0>, cudaFuncAttributeMaxDynamicSharedMemorySize, DYN_SMEM);
    cudaFuncSetAttribute(phi_gemm<1>, cudaFuncAttributeMaxDynamicSharedMemorySize, DYN_SMEM);

    // prep
    zero_init_kernel<<<512, 256>>>();
    split_x_kernel<<<(MPHI * DIN / 2 + 255) / 256, 256>>>(x, MPHI * DIN / 2);
    transpose_split_kernel<0><<<dim3(DH / 32, DIN / 32), dim3(32, 8)>>>(W1, DIN, DH);
    transpose_split_kernel<1><<<dim3(DH / 32, DH / 32),  dim3(32, 8)>>>(W2, DH, DH);

    // phi layer 1: h1 = relu(x @ W1 + b1), split to bf16 hi/lo
    phi_gemm<0><<<dim3(DH / BN, MPHI / BM), 256, DYN_SMEM>>>(b1, DIN, DIN / BK);
    // phi layer 2 + fused sum/max pooling
    phi_gemm<1><<<dim3(DH / BN, MPHI / BM), 256, DYN_SMEM>>>(b2, DH, DH / BK);

    // rho
    rho_partial<0><<<dim3(DH / 32, 8), 256>>>(Wr1);   // K=2048, 8 splits
    bias_relu_kernel<0><<<BB * DH / 256, 256>>>(br1, nullptr);
    rho_partial<1><<<dim3(DH / 32, 4), 256>>>(Wr2);   // K=1024, 4 splits
    bias_relu_kernel<1><<<BB * DH / 256, 256>>>(br2, out);
}

// round 6
// speedup vs baseline: 3.2697x; 1.2793x over previous
#include <cuda_runtime.h>
#include <cuda_fp16.h>
#include <cstdint>

// ---------------------------------------------------------------------------
// Problem dims
// ---------------------------------------------------------------------------
#define BB   64
#define NSET 512
#define DIN  512
#define DH   1024
#define MPHI (BB * NSET)   // 32768

// GEMM tiling: CTA 128x256, BK=64, warp tile 64x64 (2x4 warps)
#define BM 128
#define BN 256
#define BK 64

// ---------------------------------------------------------------------------
// Device scratch (fp16 words stored as unsigned short)
// ---------------------------------------------------------------------------
__device__ unsigned short g_x_hi[(size_t)MPHI * DIN];
__device__ unsigned short g_x_lo[(size_t)MPHI * DIN];
__device__ unsigned short g_w1t_hi[(size_t)DH * DIN];    // [N, K]
__device__ unsigned short g_w1t_lo[(size_t)DH * DIN];
__device__ unsigned short g_w2t_hi[(size_t)DH * DH];
__device__ unsigned short g_w2t_lo[(size_t)DH * DH];
__device__ unsigned short g_h1[(size_t)MPHI * DH];       // single fp16 word
__device__ float g_pooled[BB * 2 * DH];
__device__ float g_racc1[BB * DH];
__device__ float g_racc2[BB * DH];
__device__ float g_r1[BB * DH];

// ---------------------------------------------------------------------------
// PTX helpers
// ---------------------------------------------------------------------------
__device__ __forceinline__ uint32_t smem_u32(const void* p) {
    uint32_t a;
    asm("{ .reg .u64 t; cvta.to.shared.u64 t, %1; cvt.u32.u64 %0, t; }"
        : "=r"(a) : "l"(p));
    return a;
}

__device__ __forceinline__ void cp16(uint32_t dst, const void* src) {
    asm volatile("cp.async.cg.shared.global [%0], [%1], 16;"
                 :: "r"(dst), "l"(src));
}
#define CP_COMMIT() asm volatile("cp.async.commit_group;" ::: "memory")
#define CP_WAIT(n)  asm volatile("cp.async.wait_group %0;" :: "n"(n) : "memory")

__device__ __forceinline__ void ldsm_x4(uint32_t& r0, uint32_t& r1,
                                        uint32_t& r2, uint32_t& r3, uint32_t addr) {
    asm volatile("ldmatrix.sync.aligned.m8n8.x4.shared.b16 {%0,%1,%2,%3}, [%4];"
                 : "=r"(r0), "=r"(r1), "=r"(r2), "=r"(r3) : "r"(addr));
}

__device__ __forceinline__ void mma16816(float* c, const uint32_t* a, const uint32_t* b) {
    asm volatile(
        "mma.sync.aligned.m16n8k16.row.col.f32.f16.f16.f32 "
        "{%0,%1,%2,%3}, {%4,%5,%6,%7}, {%8,%9}, {%0,%1,%2,%3};"
        : "+f"(c[0]), "+f"(c[1]), "+f"(c[2]), "+f"(c[3])
        : "r"(a[0]), "r"(a[1]), "r"(a[2]), "r"(a[3]), "r"(b[0]), "r"(b[1]));
}

__device__ __forceinline__ uint32_t pack_h2(float v0, float v1) {
    __half h0 = __float2half_rn(v0);
    __half h1 = __float2half_rn(v1);
    return ((uint32_t)__half_as_ushort(h1) << 16) | (uint32_t)__half_as_ushort(h0);
}

// ---------------------------------------------------------------------------
// HMMA fp16 GEMM.
// MODE 0 (layer1): A = x (hi+lo fp16), B = W1t (hi+lo), 3-term; store h1 fp16.
// MODE 1 (layer2): A = h1 (single fp16), B = W2t (hi+lo), 2-term; fused pooling.
// CTA 128x256, BK=64, 2-stage cp.async, 8 warps (2m x 4n), warp tile 64x64.
// B fragments are streamed (not held) to keep register pressure < 200.
// ---------------------------------------------------------------------------
template <int MODE>
__global__ void __launch_bounds__(256, 1)
phi_gemm(const float* __restrict__ bias, int K, int C)
{
    // smem layout (per stage)
    constexpr int OFFAH = 0;
    constexpr int OFFAL = 16384;                         // MODE 0 only
    constexpr int OFFBH = (MODE == 0) ? 32768 : 16384;
    constexpr int OFFBL = OFFBH + 32768;
    constexpr int STG   = OFFBL + 32768;                 // 96KB / 80KB

    extern __shared__ char dsm[];
    __shared__ float sbias[BN];
    __shared__ float sSum[2][BN], sMax[2][BN];

    const int tid  = threadIdx.x;
    const int lane = tid & 31;
    const int wid  = tid >> 5;
    const int wm   = wid >> 2;     // 0..1
    const int wn   = wid & 3;      // 0..3
    const int rowBlk = blockIdx.y * BM;
    const int colBlk = blockIdx.x * BN;

    const unsigned short* Ahi = (MODE == 0) ? g_x_hi : g_h1;
    const unsigned short* Alo = g_x_lo;                          // MODE 0 only
    const unsigned short* Bhi = (MODE == 0) ? g_w1t_hi : g_w2t_hi;
    const unsigned short* Blo = (MODE == 0) ? g_w1t_lo : g_w2t_lo;

    const uint32_t sb = (smem_u32(dsm) + 1023u) & ~1023u;

    if (tid < BN) sbias[tid] = bias[colBlk + tid];

    float acc[4][8][4];
#pragma unroll
    for (int i = 0; i < 4; i++)
#pragma unroll
        for (int j = 0; j < 8; j++)
#pragma unroll
            for (int k = 0; k < 4; k++) acc[i][j][k] = 0.f;

    // ldmatrix per-thread addressing (swizzled 128B rows)
    const int arow = wm * 64 + (lane & 15);
    const uint32_t aRowOff = (uint32_t)arow * 128;
    const uint32_t aXor = ((uint32_t)(arow & 7)) << 4;
    const int brow = wn * 64 + (lane & 15);
    const uint32_t bRowOff = (uint32_t)brow * 128;
    const uint32_t bXor = ((uint32_t)(brow & 7)) << 4;
    const uint32_t csel = ((uint32_t)((lane >> 4) & 1)) << 4;

    // stage loader
    auto load_chunk = [&](int stage, int kt) {
        uint32_t st = sb + stage * STG;
#pragma unroll
        for (int l = 0; l < 4; l++) {               // A: 128 rows x 64k
            int f = tid + l * 256;
            int r = f >> 3, q = f & 7;
            uint32_t off = (uint32_t)(r * 128) +
                           (((uint32_t)(q * 16)) ^ (((uint32_t)(r & 7)) << 4));
            size_t ga = (size_t)(rowBlk + r) * K + kt + q * 8;
            cp16(st + OFFAH + off, Ahi + ga);
            if (MODE == 0) cp16(st + OFFAL + off, Alo + ga);
        }
#pragma unroll
        for (int l = 0; l < 8; l++) {               // B: 256 rows x 64k
            int f = tid + l * 256;
            int r = f >> 3, q = f & 7;
            uint32_t off = (uint32_t)(r * 128) +
                           (((uint32_t)(q * 16)) ^ (((uint32_t)(r & 7)) << 4));
            size_t gb = (size_t)(colBlk + r) * K + kt + q * 8;
            cp16(st + OFFBH + off, Bhi + gb);
            cp16(st + OFFBL + off, Blo + gb);
        }
        CP_COMMIT();
    };

    load_chunk(0, 0);
    load_chunk(1, BK);

    for (int c = 0; c < C; c++) {
        if (c + 1 < C) { CP_WAIT(1); } else { CP_WAIT(0); }
        __syncthreads();

        const uint32_t st = sb + (c & 1) * STG;
#pragma unroll
        for (int k16 = 0; k16 < 4; k16++) {
            const uint32_t cb = k16 * 32;
            uint32_t ah[4][4], al[4][4];
#pragma unroll
            for (int mi = 0; mi < 4; mi++) {
                uint32_t aoff = aRowOff + mi * 2048 + ((cb + csel) ^ aXor);
                ldsm_x4(ah[mi][0], ah[mi][1], ah[mi][2], ah[mi][3], st + OFFAH + aoff);
                if (MODE == 0)
                    ldsm_x4(al[mi][0], al[mi][1], al[mi][2], al[mi][3],
                            st + OFFAL + aoff);
            }
            // stream B two columns (one ldsm.x4 pair) at a time
#pragma unroll
            for (int nb = 0; nb < 4; nb++) {
                uint32_t boff = bRowOff + nb * 2048 + ((cb + csel) ^ bXor);
                uint32_t bh[2][2], bl[2][2];
                uint32_t r0, r1, r2, r3;
                ldsm_x4(r0, r1, r2, r3, st + OFFBH + boff);
                bh[0][0] = r0; bh[0][1] = r2; bh[1][0] = r1; bh[1][1] = r3;
                ldsm_x4(r0, r1, r2, r3, st + OFFBL + boff);
                bl[0][0] = r0; bl[0][1] = r2; bl[1][0] = r1; bl[1][1] = r3;
#pragma unroll
                for (int mi = 0; mi < 4; mi++)
#pragma unroll
                    for (int nj = 0; nj < 2; nj++) {
                        float* a4 = acc[mi][nb * 2 + nj];
                        mma16816(a4, ah[mi], bh[nj]);               // hi*hi
                        mma16816(a4, ah[mi], bl[nj]);               // hi*lo
                        if (MODE == 0) mma16816(a4, al[mi], bh[nj]); // lo*hi
                    }
            }
        }
        __syncthreads();
        if (c + 2 < C) load_chunk(c & 1, (c + 2) * BK);
    }

    // ------------------------- epilogue -------------------------
    const int r0base = wm * 64 + (lane >> 2);
    const int n0base = wn * 64 + 2 * (lane & 3);

    if (MODE == 0) {
        // relu + single-word fp16 store of h1
#pragma unroll
        for (int mi = 0; mi < 4; mi++) {
            int r0 = rowBlk + r0base + mi * 16;
#pragma unroll
            for (int ni = 0; ni < 8; ni++) {
                int nrel = n0base + ni * 8;
                float b0 = sbias[nrel], b1 = sbias[nrel + 1];
                float v00 = fmaxf(acc[mi][ni][0] + b0, 0.f);
                float v01 = fmaxf(acc[mi][ni][1] + b1, 0.f);
                float v10 = fmaxf(acc[mi][ni][2] + b0, 0.f);
                float v11 = fmaxf(acc[mi][ni][3] + b1, 0.f);
                *(uint32_t*)&g_h1[(size_t)r0 * DH + colBlk + nrel] = pack_h2(v00, v01);
                *(uint32_t*)&g_h1[(size_t)(r0 + 8) * DH + colBlk + nrel] = pack_h2(v10, v11);
            }
        }
    } else {
        const int bIdx = rowBlk >> 9;   // 512 rows per batch, 128 | 512
        float s[8][2], mx[8][2];
#pragma unroll
        for (int ni = 0; ni < 8; ni++) { s[ni][0] = s[ni][1] = 0.f;
                                         mx[ni][0] = mx[ni][1] = 0.f; }
#pragma unroll
        for (int mi = 0; mi < 4; mi++)
#pragma unroll
            for (int ni = 0; ni < 8; ni++) {
                int nrel = n0base + ni * 8;
                float b0 = sbias[nrel], b1 = sbias[nrel + 1];
                float v00 = fmaxf(acc[mi][ni][0] + b0, 0.f);
                float v01 = fmaxf(acc[mi][ni][1] + b1, 0.f);
                float v10 = fmaxf(acc[mi][ni][2] + b0, 0.f);
                float v11 = fmaxf(acc[mi][ni][3] + b1, 0.f);
                s[ni][0] += v00 + v10;  s[ni][1] += v01 + v11;
                mx[ni][0] = fmaxf(mx[ni][0], fmaxf(v00, v10));
                mx[ni][1] = fmaxf(mx[ni][1], fmaxf(v01, v11));
            }
#pragma unroll
        for (int o = 4; o < 32; o <<= 1)
#pragma unroll
            for (int ni = 0; ni < 8; ni++)
#pragma unroll
                for (int j = 0; j < 2; j++) {
                    s[ni][j]  += __shfl_xor_sync(0xffffffffu, s[ni][j], o);
                    mx[ni][j]  = fmaxf(mx[ni][j],
                                       __shfl_xor_sync(0xffffffffu, mx[ni][j], o));
                }
        if ((lane >> 2) == 0) {
#pragma unroll
            for (int ni = 0; ni < 8; ni++)
#pragma unroll
                for (int j = 0; j < 2; j++) {
                    int col = wn * 64 + ni * 8 + 2 * lane + j;
                    sSum[wm][col] = s[ni][j];
                    sMax[wm][col] = mx[ni][j];
                }
        }
        __syncthreads();
        {
            float S = sSum[0][tid] + sSum[1][tid];
            float M = fmaxf(sMax[0][tid], sMax[1][tid]);
            atomicAdd(&g_pooled[bIdx * 2 * DH + colBlk + tid], S);
            atomicMax((int*)&g_pooled[bIdx * 2 * DH + DH + colBlk + tid],
                      __float_as_int(M));
        }
    }
}

// ---------------------------------------------------------------------------
// Prep kernels
// ---------------------------------------------------------------------------
__global__ void zero_init_kernel() {
    int i = blockIdx.x * 256 + threadIdx.x;
    if (i < BB * 2 * DH) g_pooled[i] = 0.f;
    if (i < BB * DH) { g_racc1[i] = 0.f; g_racc2[i] = 0.f; }
}

__global__ void split_x_kernel(const float* __restrict__ src, int n2) {
    int i = blockIdx.x * 256 + threadIdx.x;
    if (i >= n2) return;
    float2 v = ((const float2*)src)[i];
    __half h0 = __float2half_rn(v.x);
    __half h1 = __float2half_rn(v.y);
    __half l0 = __float2half_rn(v.x - __half2float(h0));
    __half l1 = __float2half_rn(v.y - __half2float(h1));
    ((uint32_t*)g_x_hi)[i] = ((uint32_t)__half_as_ushort(h1) << 16)
                           | (uint32_t)__half_as_ushort(h0);
    ((uint32_t*)g_x_lo)[i] = ((uint32_t)__half_as_ushort(l1) << 16)
                           | (uint32_t)__half_as_ushort(l0);
}

// src [R, Cn] fp32 -> dst [Cn, R] fp16 hi/lo
template <int WSEL>
__global__ void transpose_split_kernel(const float* __restrict__ src, int R, int Cn) {
    __shared__ float t[32][33];
    unsigned short* dhi = (WSEL == 0) ? g_w1t_hi : g_w2t_hi;
    unsigned short* dlo = (WSEL == 0) ? g_w1t_lo : g_w2t_lo;
    int bx = blockIdx.x * 32, by = blockIdx.y * 32;
    int tx = threadIdx.x, ty = threadIdx.y;
#pragma unroll
    for (int i = 0; i < 32; i += 8)
        t[ty + i][tx] = src[(size_t)(by + ty + i) * Cn + bx + tx];
    __syncthreads();
#pragma unroll
    for (int i = 0; i < 32; i += 8) {
        float v = t[tx][ty + i];
        int n = bx + ty + i, k = by + tx;
        __half h = __float2half_rn(v);
        dhi[(size_t)n * R + k] = __half_as_ushort(h);
        dlo[(size_t)n * R + k] = __half_as_ushort(
            __float2half_rn(v - __half2float(h)));
    }
}

// ---------------------------------------------------------------------------
// rho GEMMs: split-K FFMA with atomic fp32 accumulation.
// ---------------------------------------------------------------------------
template <int PHASE>
__global__ void __launch_bounds__(256)
rho_partial(const float* __restrict__ W)
{
    const int lda = (PHASE == 0) ? 2 * DH : DH;
    const float* A = (PHASE == 0) ? (const float*)g_pooled : (const float*)g_r1;
    float* acc     = (PHASE == 0) ? g_racc1 : g_racc2;

    __shared__ float As[64][65];
    const int tid = threadIdx.x;
    const int tx = tid & 31, ty = tid >> 5;
    const int col = blockIdx.x * 32 + tx;
    const int k0 = blockIdx.y * 256;

    float a8[8];
#pragma unroll
    for (int r = 0; r < 8; r++) a8[r] = 0.f;

    for (int kt = k0; kt < k0 + 256; kt += 64) {
#pragma unroll
        for (int l = 0; l < 4; l++) {
            int f = tid + l * 256;
            int row = f >> 4, q = f & 15;
            float4 v = *reinterpret_cast<const float4*>(
                &A[(size_t)row * lda + kt + q * 4]);
            As[row][q * 4 + 0] = v.x; As[row][q * 4 + 1] = v.y;
            As[row][q * 4 + 2] = v.z; As[row][q * 4 + 3] = v.w;
        }
        __syncthreads();
#pragma unroll
        for (int kk = 0; kk < 64; kk++) {
            float w = W[(size_t)(kt + kk) * DH + col];
#pragma unroll
            for (int r = 0; r < 8; r++) a8[r] += As[ty * 8 + r][kk] * w;
        }
        __syncthreads();
    }
#pragma unroll
    for (int r = 0; r < 8; r++)
        atomicAdd(&acc[(size_t)(ty * 8 + r) * DH + col], a8[r]);
}

template <int PHASE>
__global__ void bias_relu_kernel(const float* __restrict__ b, float* __restrict__ outp) {
    int i = blockIdx.x * 256 + threadIdx.x;
    const float* acc = (PHASE == 0) ? g_racc1 : g_racc2;
    float* out = (PHASE == 0) ? g_r1 : outp;
    out[i] = fmaxf(acc[i] + b[i & (DH - 1)], 0.f);
}

// ---------------------------------------------------------------------------
// Launch
// ---------------------------------------------------------------------------
extern "C" void kernel_launch(void* const* d_in, const int* in_sizes, int n_in,
                              void* d_out, int out_size)
{
    const float* x   = (const float*)d_in[0];
    const float* W1  = (const float*)d_in[1];
    const float* b1  = (const float*)d_in[2];
    const float* W2  = (const float*)d_in[3];
    const float* b2  = (const float*)d_in[4];
    const float* Wr1 = (const float*)d_in[5];
    const float* br1 = (const float*)d_in[6];
    const float* Wr2 = (const float*)d_in[7];
    const float* br2 = (const float*)d_in[8];
    float* out       = (float*)d_out;

    const int SMEM0 = 2 * 98304 + 1024;   // MODE 0: 96KB stages
    const int SMEM1 = 2 * 81920 + 1024;   // MODE 1: 80KB stages
    cudaFuncSetAttribute(phi_gemm<0>, cudaFuncAttributeMaxDynamicSharedMemorySize, SMEM0);
    cudaFuncSetAttribute(phi_gemm<1>, cudaFuncAttributeMaxDynamicSharedMemorySize, SMEM1);

    // prep
    zero_init_kernel<<<512, 256>>>();
    split_x_kernel<<<(MPHI * DIN / 2 + 255) / 256, 256>>>(x, MPHI * DIN / 2);
    transpose_split_kernel<0><<<dim3(DH / 32, DIN / 32), dim3(32, 8)>>>(W1, DIN, DH);
    transpose_split_kernel<1><<<dim3(DH / 32, DH / 32),  dim3(32, 8)>>>(W2, DH, DH);

    // phi layer 1 (3-term fp16): h1 = relu(x @ W1 + b1) -> fp16
    phi_gemm<0><<<dim3(DH / BN, MPHI / BM), 256, SMEM0>>>(b1, DIN, DIN / BK);
    // phi layer 2 (2-term fp16) + fused sum/max pooling
    phi_gemm<1><<<dim3(DH / BN, MPHI / BM), 256, SMEM1>>>(b2, DH, DH / BK);

    // rho
    rho_partial<0><<<dim3(DH / 32, 8), 256>>>(Wr1);   // K=2048, 8 splits
    bias_relu_kernel<0><<<BB * DH / 256, 256>>>(br1, nullptr);
    rho_partial<1><<<dim3(DH / 32, 4), 256>>>(Wr2);   // K=1024, 4 splits
    bias_relu_kernel<1><<<BB * DH / 256, 256>>>(br2, out);
}

// round 7
// speedup vs baseline: 5.6384x; 1.7244x over previous
#include <cuda_runtime.h>
#include <cuda_fp16.h>
#include <cstdint>

// ---------------------------------------------------------------------------
// Problem dims
// ---------------------------------------------------------------------------
#define BB   64
#define NSET 512
#define DIN  512
#define DH   1024
#define MPHI (BB * NSET)   // 32768

// GEMM tiling: CTA 128x256, BK=64, warp tile 64x64 (2x4 warps), 4 stages
#define BM 128
#define BN 256
#define BK 64
#define OFFB 16384
#define STG  49152
#define NSTAGE 4
#define DYN_SMEM (NSTAGE * STG + 1024)

// ---------------------------------------------------------------------------
// Device scratch (fp16 words as unsigned short)
// ---------------------------------------------------------------------------
__device__ unsigned short g_x16[(size_t)MPHI * DIN];     // x as fp16
__device__ unsigned short g_w1t[(size_t)DH * DIN];       // W1^T [N,K] fp16
__device__ unsigned short g_w2t[(size_t)DH * DH];        // W2^T [N,K] fp16
__device__ unsigned short g_h1[(size_t)MPHI * DH];       // h1 fp16
__device__ float g_pooled[BB * 2 * DH];
__device__ float g_racc1[BB * DH];
__device__ float g_racc2[BB * DH];
__device__ float g_r1[BB * DH];

// ---------------------------------------------------------------------------
// PTX helpers
// ---------------------------------------------------------------------------
__device__ __forceinline__ uint32_t smem_u32(const void* p) {
    uint32_t a;
    asm("{ .reg .u64 t; cvta.to.shared.u64 t, %1; cvt.u32.u64 %0, t; }"
        : "=r"(a) : "l"(p));
    return a;
}

__device__ __forceinline__ void cp16(uint32_t dst, const void* src) {
    asm volatile("cp.async.cg.shared.global [%0], [%1], 16;"
                 :: "r"(dst), "l"(src));
}
#define CP_COMMIT() asm volatile("cp.async.commit_group;" ::: "memory")
#define CP_WAIT(n)  asm volatile("cp.async.wait_group %0;" :: "n"(n) : "memory")

__device__ __forceinline__ void ldsm_x4(uint32_t& r0, uint32_t& r1,
                                        uint32_t& r2, uint32_t& r3, uint32_t addr) {
    asm volatile("ldmatrix.sync.aligned.m8n8.x4.shared.b16 {%0,%1,%2,%3}, [%4];"
                 : "=r"(r0), "=r"(r1), "=r"(r2), "=r"(r3) : "r"(addr));
}

__device__ __forceinline__ void mma16816(float* c, const uint32_t* a, const uint32_t* b) {
    asm volatile(
        "mma.sync.aligned.m16n8k16.row.col.f32.f16.f16.f32 "
        "{%0,%1,%2,%3}, {%4,%5,%6,%7}, {%8,%9}, {%0,%1,%2,%3};"
        : "+f"(c[0]), "+f"(c[1]), "+f"(c[2]), "+f"(c[3])
        : "r"(a[0]), "r"(a[1]), "r"(a[2]), "r"(a[3]), "r"(b[0]), "r"(b[1]));
}

__device__ __forceinline__ uint32_t pack_h2(float v0, float v1) {
    __half h0 = __float2half_rn(v0);
    __half h1 = __float2half_rn(v1);
    return ((uint32_t)__half_as_ushort(h1) << 16) | (uint32_t)__half_as_ushort(h0);
}

// ---------------------------------------------------------------------------
// Pure fp16 HMMA GEMM, 4-stage cp.async pipeline.
// MODE 0 (layer1): A = x16, B = W1t; epilogue stores h1 fp16.
// MODE 1 (layer2): A = h1,  B = W2t; epilogue fuses sum/max pooling.
// CTA 128x256, 8 warps (2m x 4n), warp tile 64x64.
// ---------------------------------------------------------------------------
template <int MODE>
__global__ void __launch_bounds__(256, 1)
phi_gemm(const float* __restrict__ bias, int K, int C)
{
    extern __shared__ char dsm[];
    __shared__ float sbias[BN];
    __shared__ float sSum[2][BN], sMax[2][BN];

    const int tid  = threadIdx.x;
    const int lane = tid & 31;
    const int wid  = tid >> 5;
    const int wm   = wid >> 2;     // 0..1
    const int wn   = wid & 3;      // 0..3
    const int rowBlk = blockIdx.y * BM;
    const int colBlk = blockIdx.x * BN;

    const unsigned short* A = (MODE == 0) ? g_x16 : g_h1;
    const unsigned short* Bm = (MODE == 0) ? g_w1t : g_w2t;

    const uint32_t sb = (smem_u32(dsm) + 1023u) & ~1023u;

    if (tid < BN) sbias[tid] = bias[colBlk + tid];

    float acc[4][8][4];
#pragma unroll
    for (int i = 0; i < 4; i++)
#pragma unroll
        for (int j = 0; j < 8; j++)
#pragma unroll
            for (int k = 0; k < 4; k++) acc[i][j][k] = 0.f;

    // ldmatrix per-thread addressing (swizzled 128B rows)
    const int arow = wm * 64 + (lane & 15);
    const uint32_t aRowOff = (uint32_t)arow * 128;
    const uint32_t aXor = ((uint32_t)(arow & 7)) << 4;
    const int brow = wn * 64 + (lane & 15);
    const uint32_t bRowOff = (uint32_t)brow * 128;
    const uint32_t bXor = ((uint32_t)(brow & 7)) << 4;
    const uint32_t csel = ((uint32_t)((lane >> 4) & 1)) << 4;

    // stage loader: A 128x64 (16KB) + B 256x64 (32KB)
    auto load_chunk = [&](int stage, int kt) {
        uint32_t st = sb + stage * STG;
#pragma unroll
        for (int l = 0; l < 4; l++) {
            int f = tid + l * 256;
            int r = f >> 3, q = f & 7;
            uint32_t off = (uint32_t)(r * 128) +
                           (((uint32_t)(q * 16)) ^ (((uint32_t)(r & 7)) << 4));
            cp16(st + off, A + (size_t)(rowBlk + r) * K + kt + q * 8);
        }
#pragma unroll
        for (int l = 0; l < 8; l++) {
            int f = tid + l * 256;
            int r = f >> 3, q = f & 7;
            uint32_t off = (uint32_t)(r * 128) +
                           (((uint32_t)(q * 16)) ^ (((uint32_t)(r & 7)) << 4));
            cp16(st + OFFB + off, Bm + (size_t)(colBlk + r) * K + kt + q * 8);
        }
        CP_COMMIT();
    };

    // prologue: 3 chunks in flight
    load_chunk(0, 0);
    if (C > 1) load_chunk(1, BK);
    if (C > 2) load_chunk(2, 2 * BK);

    for (int c = 0; c < C; c++) {
        if (c + 2 < C)      { CP_WAIT(2); }
        else if (c + 1 < C) { CP_WAIT(1); }
        else                { CP_WAIT(0); }
        __syncthreads();
        // stage (c+3)%4 was consumed at iter c-1 and barrier-separated: safe
        if (c + 3 < C) load_chunk((c + 3) & (NSTAGE - 1), (c + 3) * BK);

        const uint32_t st = sb + (c & (NSTAGE - 1)) * STG;
#pragma unroll
        for (int k16 = 0; k16 < 4; k16++) {
            const uint32_t cb = k16 * 32;
            uint32_t ah[4][4];
#pragma unroll
            for (int mi = 0; mi < 4; mi++) {
                uint32_t aoff = aRowOff + mi * 2048 + ((cb + csel) ^ aXor);
                ldsm_x4(ah[mi][0], ah[mi][1], ah[mi][2], ah[mi][3], st + aoff);
            }
#pragma unroll
            for (int nb = 0; nb < 4; nb++) {
                uint32_t boff = bRowOff + nb * 2048 + ((cb + csel) ^ bXor);
                uint32_t b0, b1, b2, b3;
                ldsm_x4(b0, b1, b2, b3, st + OFFB + boff);
                uint32_t bfr0[2] = {b0, b2};
                uint32_t bfr1[2] = {b1, b3};
#pragma unroll
                for (int mi = 0; mi < 4; mi++) {
                    mma16816(acc[mi][nb * 2],     ah[mi], bfr0);
                    mma16816(acc[mi][nb * 2 + 1], ah[mi], bfr1);
                }
            }
        }
    }

    // ------------------------- epilogue -------------------------
    const int r0base = wm * 64 + (lane >> 2);
    const int n0base = wn * 64 + 2 * (lane & 3);

    if (MODE == 0) {
#pragma unroll
        for (int mi = 0; mi < 4; mi++) {
            int r0 = rowBlk + r0base + mi * 16;
#pragma unroll
            for (int ni = 0; ni < 8; ni++) {
                int nrel = n0base + ni * 8;
                float b0 = sbias[nrel], b1 = sbias[nrel + 1];
                float v00 = fmaxf(acc[mi][ni][0] + b0, 0.f);
                float v01 = fmaxf(acc[mi][ni][1] + b1, 0.f);
                float v10 = fmaxf(acc[mi][ni][2] + b0, 0.f);
                float v11 = fmaxf(acc[mi][ni][3] + b1, 0.f);
                *(uint32_t*)&g_h1[(size_t)r0 * DH + colBlk + nrel] = pack_h2(v00, v01);
                *(uint32_t*)&g_h1[(size_t)(r0 + 8) * DH + colBlk + nrel] = pack_h2(v10, v11);
            }
        }
    } else {
        const int bIdx = rowBlk >> 9;   // 512 rows per batch, 128 | 512
        float s[8][2], mx[8][2];
#pragma unroll
        for (int ni = 0; ni < 8; ni++) { s[ni][0] = s[ni][1] = 0.f;
                                         mx[ni][0] = mx[ni][1] = 0.f; }
#pragma unroll
        for (int mi = 0; mi < 4; mi++)
#pragma unroll
            for (int ni = 0; ni < 8; ni++) {
                int nrel = n0base + ni * 8;
                float b0 = sbias[nrel], b1 = sbias[nrel + 1];
                float v00 = fmaxf(acc[mi][ni][0] + b0, 0.f);
                float v01 = fmaxf(acc[mi][ni][1] + b1, 0.f);
                float v10 = fmaxf(acc[mi][ni][2] + b0, 0.f);
                float v11 = fmaxf(acc[mi][ni][3] + b1, 0.f);
                s[ni][0] += v00 + v10;  s[ni][1] += v01 + v11;
                mx[ni][0] = fmaxf(mx[ni][0], fmaxf(v00, v10));
                mx[ni][1] = fmaxf(mx[ni][1], fmaxf(v01, v11));
            }
#pragma unroll
        for (int o = 4; o < 32; o <<= 1)
#pragma unroll
            for (int ni = 0; ni < 8; ni++)
#pragma unroll
                for (int j = 0; j < 2; j++) {
                    s[ni][j]  += __shfl_xor_sync(0xffffffffu, s[ni][j], o);
                    mx[ni][j]  = fmaxf(mx[ni][j],
                                       __shfl_xor_sync(0xffffffffu, mx[ni][j], o));
                }
        if ((lane >> 2) == 0) {
#pragma unroll
            for (int ni = 0; ni < 8; ni++)
#pragma unroll
                for (int j = 0; j < 2; j++) {
                    int col = wn * 64 + ni * 8 + 2 * lane + j;
                    sSum[wm][col] = s[ni][j];
                    sMax[wm][col] = mx[ni][j];
                }
        }
        __syncthreads();
        {
            float S = sSum[0][tid] + sSum[1][tid];
            float M = fmaxf(sMax[0][tid], sMax[1][tid]);
            atomicAdd(&g_pooled[bIdx * 2 * DH + colBlk + tid], S);
            atomicMax((int*)&g_pooled[bIdx * 2 * DH + DH + colBlk + tid],
                      __float_as_int(M));
        }
    }
}

// ---------------------------------------------------------------------------
// Prep kernels
// ---------------------------------------------------------------------------
__global__ void zero_init_kernel() {
    int i = blockIdx.x * 256 + threadIdx.x;
    if (i < BB * 2 * DH) g_pooled[i] = 0.f;
    if (i < BB * DH) { g_racc1[i] = 0.f; g_racc2[i] = 0.f; }
}

__global__ void cvt_x_kernel(const float* __restrict__ src, int n2) {
    int i = blockIdx.x * 256 + threadIdx.x;
    if (i >= n2) return;
    float2 v = ((const float2*)src)[i];
    ((uint32_t*)g_x16)[i] = pack_h2(v.x, v.y);
}

// src [R, Cn] fp32 -> dst [Cn, R] fp16
template <int WSEL>
__global__ void transpose_cvt_kernel(const float* __restrict__ src, int R, int Cn) {
    __shared__ float t[32][33];
    unsigned short* dst = (WSEL == 0) ? g_w1t : g_w2t;
    int bx = blockIdx.x * 32, by = blockIdx.y * 32;
    int tx = threadIdx.x, ty = threadIdx.y;
#pragma unroll
    for (int i = 0; i < 32; i += 8)
        t[ty + i][tx] = src[(size_t)(by + ty + i) * Cn + bx + tx];
    __syncthreads();
#pragma unroll
    for (int i = 0; i < 32; i += 8) {
        int n = bx + ty + i, k = by + tx;
        dst[(size_t)n * R + k] = __half_as_ushort(__float2half_rn(t[tx][ty + i]));
    }
}

// ---------------------------------------------------------------------------
// rho GEMMs: split-K FFMA with atomic fp32 accumulation (exact fp32 path).
// ---------------------------------------------------------------------------
template <int PHASE>
__global__ void __launch_bounds__(256)
rho_partial(const float* __restrict__ W)
{
    const int lda = (PHASE == 0) ? 2 * DH : DH;
    const float* A = (PHASE == 0) ? (const float*)g_pooled : (const float*)g_r1;
    float* acc     = (PHASE == 0) ? g_racc1 : g_racc2;

    __shared__ float As[64][65];
    const int tid = threadIdx.x;
    const int tx = tid & 31, ty = tid >> 5;
    const int col = blockIdx.x * 32 + tx;
    const int k0 = blockIdx.y * 256;

    float a8[8];
#pragma unroll
    for (int r = 0; r < 8; r++) a8[r] = 0.f;

    for (int kt = k0; kt < k0 + 256; kt += 64) {
#pragma unroll
        for (int l = 0; l < 4; l++) {
            int f = tid + l * 256;
            int row = f >> 4, q = f & 15;
            float4 v = *reinterpret_cast<const float4*>(
                &A[(size_t)row * lda + kt + q * 4]);
            As[row][q * 4 + 0] = v.x; As[row][q * 4 + 1] = v.y;
            As[row][q * 4 + 2] = v.z; As[row][q * 4 + 3] = v.w;
        }
        __syncthreads();
#pragma unroll
        for (int kk = 0; kk < 64; kk++) {
            float w = W[(size_t)(kt + kk) * DH + col];
#pragma unroll
            for (int r = 0; r < 8; r++) a8[r] += As[ty * 8 + r][kk] * w;
        }
        __syncthreads();
    }
#pragma unroll
    for (int r = 0; r < 8; r++)
        atomicAdd(&acc[(size_t)(ty * 8 + r) * DH + col], a8[r]);
}

template <int PHASE>
__global__ void bias_relu_kernel(const float* __restrict__ b, float* __restrict__ outp) {
    int i = blockIdx.x * 256 + threadIdx.x;
    const float* acc = (PHASE == 0) ? g_racc1 : g_racc2;
    float* out = (PHASE == 0) ? g_r1 : outp;
    out[i] = fmaxf(acc[i] + b[i & (DH - 1)], 0.f);
}

// ---------------------------------------------------------------------------
// Launch
// ---------------------------------------------------------------------------
extern "C" void kernel_launch(void* const* d_in, const int* in_sizes, int n_in,
                              void* d_out, int out_size)
{
    const float* x   = (const float*)d_in[0];
    const float* W1  = (const float*)d_in[1];
    const float* b1  = (const float*)d_in[2];
    const float* W2  = (const float*)d_in[3];
    const float* b2  = (const float*)d_in[4];
    const float* Wr1 = (const float*)d_in[5];
    const float* br1 = (const float*)d_in[6];
    const float* Wr2 = (const float*)d_in[7];
    const float* br2 = (const float*)d_in[8];
    float* out       = (float*)d_out;

    cudaFuncSetAttribute(phi_gemm<0>, cudaFuncAttributeMaxDynamicSharedMemorySize, DYN_SMEM);
    cudaFuncSetAttribute(phi_gemm<1>, cudaFuncAttributeMaxDynamicSharedMemorySize, DYN_SMEM);

    // prep
    zero_init_kernel<<<512, 256>>>();
    cvt_x_kernel<<<(MPHI * DIN / 2 + 255) / 256, 256>>>(x, MPHI * DIN / 2);
    transpose_cvt_kernel<0><<<dim3(DH / 32, DIN / 32), dim3(32, 8)>>>(W1, DIN, DH);
    transpose_cvt_kernel<1><<<dim3(DH / 32, DH / 32),  dim3(32, 8)>>>(W2, DH, DH);

    // phi layer 1: h1 = relu(x @ W1 + b1) -> fp16
    phi_gemm<0><<<dim3(DH / BN, MPHI / BM), 256, DYN_SMEM>>>(b1, DIN, DIN / BK);
    // phi layer 2 + fused sum/max pooling
    phi_gemm<1><<<dim3(DH / BN, MPHI / BM), 256, DYN_SMEM>>>(b2, DH, DH / BK);

    // rho (fp32 exact)
    rho_partial<0><<<dim3(DH / 32, 8), 256>>>(Wr1);   // K=2048, 8 splits
    bias_relu_kernel<0><<<BB * DH / 256, 256>>>(br1, nullptr);
    rho_partial<1><<<dim3(DH / 32, 4), 256>>>(Wr2);   // K=1024, 4 splits
    bias_relu_kernel<1><<<BB * DH / 256, 256>>>(br2, out);
}

// round 8
// speedup vs baseline: 6.6261x; 1.1752x over previous
#include <cuda_runtime.h>
#include <cuda_fp16.h>
#include <cstdint>

// ---------------------------------------------------------------------------
// Problem dims
// ---------------------------------------------------------------------------
#define BB   64
#define NSET 512
#define DIN  512
#define DH   1024
#define MPHI (BB * NSET)   // 32768

// GEMM tiling: CTA 128x256, BK=64, warp tile 64x64 (2x4 warps), 4 stages
#define BM 128
#define BN 256
#define BK 64
#define OFFB 16384
#define STG  49152
#define NSTAGE 4
#define DYN_SMEM (NSTAGE * STG + 1024)

// ---------------------------------------------------------------------------
// Device scratch (fp16 words as unsigned short)
// ---------------------------------------------------------------------------
__device__ unsigned short g_x16[(size_t)MPHI * DIN];     // x as fp16
__device__ unsigned short g_w1t[(size_t)DH * DIN];       // W1^T [N,K] fp16
__device__ unsigned short g_w2t[(size_t)DH * DH];        // W2^T [N,K] fp16
__device__ unsigned short g_h1[(size_t)MPHI * DH];       // h1 fp16
__device__ float g_pooled[BB * 2 * DH];
__device__ float g_racc1[BB * DH];
__device__ float g_racc2[BB * DH];
__device__ float g_r1[BB * DH];

// ---------------------------------------------------------------------------
// PTX helpers
// ---------------------------------------------------------------------------
__device__ __forceinline__ uint32_t smem_u32(const void* p) {
    uint32_t a;
    asm("{ .reg .u64 t; cvta.to.shared.u64 t, %1; cvt.u32.u64 %0, t; }"
        : "=r"(a) : "l"(p));
    return a;
}

__device__ __forceinline__ void cp16(uint32_t dst, const void* src) {
    asm volatile("cp.async.cg.shared.global [%0], [%1], 16;"
                 :: "r"(dst), "l"(src));
}
#define CP_COMMIT() asm volatile("cp.async.commit_group;" ::: "memory")
#define CP_WAIT(n)  asm volatile("cp.async.wait_group %0;" :: "n"(n) : "memory")

__device__ __forceinline__ void ldsm_x4(uint32_t& r0, uint32_t& r1,
                                        uint32_t& r2, uint32_t& r3, uint32_t addr) {
    asm volatile("ldmatrix.sync.aligned.m8n8.x4.shared.b16 {%0,%1,%2,%3}, [%4];"
                 : "=r"(r0), "=r"(r1), "=r"(r2), "=r"(r3) : "r"(addr));
}

__device__ __forceinline__ void mma16816(float* c, const uint32_t* a, const uint32_t* b) {
    asm volatile(
        "mma.sync.aligned.m16n8k16.row.col.f32.f16.f16.f32 "
        "{%0,%1,%2,%3}, {%4,%5,%6,%7}, {%8,%9}, {%0,%1,%2,%3};"
        : "+f"(c[0]), "+f"(c[1]), "+f"(c[2]), "+f"(c[3])
        : "r"(a[0]), "r"(a[1]), "r"(a[2]), "r"(a[3]), "r"(b[0]), "r"(b[1]));
}

__device__ __forceinline__ uint32_t pack_h2(float v0, float v1) {
    __half h0 = __float2half_rn(v0);
    __half h1 = __float2half_rn(v1);
    return ((uint32_t)__half_as_ushort(h1) << 16) | (uint32_t)__half_as_ushort(h0);
}

// ---------------------------------------------------------------------------
// Pure fp16 HMMA GEMM, 4-stage cp.async pipeline (at legacy-HMMA HW floor).
// MODE 0 (layer1): A = x16, B = W1t; epilogue stores h1 fp16.
// MODE 1 (layer2): A = h1,  B = W2t; epilogue fuses sum/max pooling.
// ---------------------------------------------------------------------------
template <int MODE>
__global__ void __launch_bounds__(256, 1)
phi_gemm(const float* __restrict__ bias, int K, int C)
{
    extern __shared__ char dsm[];
    __shared__ float sbias[BN];
    __shared__ float sSum[2][BN], sMax[2][BN];

    const int tid  = threadIdx.x;
    const int lane = tid & 31;
    const int wid  = tid >> 5;
    const int wm   = wid >> 2;     // 0..1
    const int wn   = wid & 3;      // 0..3
    const int rowBlk = blockIdx.y * BM;
    const int colBlk = blockIdx.x * BN;

    const unsigned short* A = (MODE == 0) ? g_x16 : g_h1;
    const unsigned short* Bm = (MODE == 0) ? g_w1t : g_w2t;

    const uint32_t sb = (smem_u32(dsm) + 1023u) & ~1023u;

    if (tid < BN) sbias[tid] = bias[colBlk + tid];

    float acc[4][8][4];
#pragma unroll
    for (int i = 0; i < 4; i++)
#pragma unroll
        for (int j = 0; j < 8; j++)
#pragma unroll
            for (int k = 0; k < 4; k++) acc[i][j][k] = 0.f;

    // ldmatrix per-thread addressing (swizzled 128B rows)
    const int arow = wm * 64 + (lane & 15);
    const uint32_t aRowOff = (uint32_t)arow * 128;
    const uint32_t aXor = ((uint32_t)(arow & 7)) << 4;
    const int brow = wn * 64 + (lane & 15);
    const uint32_t bRowOff = (uint32_t)brow * 128;
    const uint32_t bXor = ((uint32_t)(brow & 7)) << 4;
    const uint32_t csel = ((uint32_t)((lane >> 4) & 1)) << 4;

    auto load_chunk = [&](int stage, int kt) {
        uint32_t st = sb + stage * STG;
#pragma unroll
        for (int l = 0; l < 4; l++) {
            int f = tid + l * 256;
            int r = f >> 3, q = f & 7;
            uint32_t off = (uint32_t)(r * 128) +
                           (((uint32_t)(q * 16)) ^ (((uint32_t)(r & 7)) << 4));
            cp16(st + off, A + (size_t)(rowBlk + r) * K + kt + q * 8);
        }
#pragma unroll
        for (int l = 0; l < 8; l++) {
            int f = tid + l * 256;
            int r = f >> 3, q = f & 7;
            uint32_t off = (uint32_t)(r * 128) +
                           (((uint32_t)(q * 16)) ^ (((uint32_t)(r & 7)) << 4));
            cp16(st + OFFB + off, Bm + (size_t)(colBlk + r) * K + kt + q * 8);
        }
        CP_COMMIT();
    };

    load_chunk(0, 0);
    if (C > 1) load_chunk(1, BK);
    if (C > 2) load_chunk(2, 2 * BK);

    for (int c = 0; c < C; c++) {
        if (c + 2 < C)      { CP_WAIT(2); }
        else if (c + 1 < C) { CP_WAIT(1); }
        else                { CP_WAIT(0); }
        __syncthreads();
        if (c + 3 < C) load_chunk((c + 3) & (NSTAGE - 1), (c + 3) * BK);

        const uint32_t st = sb + (c & (NSTAGE - 1)) * STG;
#pragma unroll
        for (int k16 = 0; k16 < 4; k16++) {
            const uint32_t cb = k16 * 32;
            uint32_t ah[4][4];
#pragma unroll
            for (int mi = 0; mi < 4; mi++) {
                uint32_t aoff = aRowOff + mi * 2048 + ((cb + csel) ^ aXor);
                ldsm_x4(ah[mi][0], ah[mi][1], ah[mi][2], ah[mi][3], st + aoff);
            }
#pragma unroll
            for (int nb = 0; nb < 4; nb++) {
                uint32_t boff = bRowOff + nb * 2048 + ((cb + csel) ^ bXor);
                uint32_t b0, b1, b2, b3;
                ldsm_x4(b0, b1, b2, b3, st + OFFB + boff);
                uint32_t bfr0[2] = {b0, b2};
                uint32_t bfr1[2] = {b1, b3};
#pragma unroll
                for (int mi = 0; mi < 4; mi++) {
                    mma16816(acc[mi][nb * 2],     ah[mi], bfr0);
                    mma16816(acc[mi][nb * 2 + 1], ah[mi], bfr1);
                }
            }
        }
    }

    // ------------------------- epilogue -------------------------
    const int r0base = wm * 64 + (lane >> 2);
    const int n0base = wn * 64 + 2 * (lane & 3);

    if (MODE == 0) {
#pragma unroll
        for (int mi = 0; mi < 4; mi++) {
            int r0 = rowBlk + r0base + mi * 16;
#pragma unroll
            for (int ni = 0; ni < 8; ni++) {
                int nrel = n0base + ni * 8;
                float b0 = sbias[nrel], b1 = sbias[nrel + 1];
                float v00 = fmaxf(acc[mi][ni][0] + b0, 0.f);
                float v01 = fmaxf(acc[mi][ni][1] + b1, 0.f);
                float v10 = fmaxf(acc[mi][ni][2] + b0, 0.f);
                float v11 = fmaxf(acc[mi][ni][3] + b1, 0.f);
                *(uint32_t*)&g_h1[(size_t)r0 * DH + colBlk + nrel] = pack_h2(v00, v01);
                *(uint32_t*)&g_h1[(size_t)(r0 + 8) * DH + colBlk + nrel] = pack_h2(v10, v11);
            }
        }
    } else {
        const int bIdx = rowBlk >> 9;
        float s[8][2], mx[8][2];
#pragma unroll
        for (int ni = 0; ni < 8; ni++) { s[ni][0] = s[ni][1] = 0.f;
                                         mx[ni][0] = mx[ni][1] = 0.f; }
#pragma unroll
        for (int mi = 0; mi < 4; mi++)
#pragma unroll
            for (int ni = 0; ni < 8; ni++) {
                int nrel = n0base + ni * 8;
                float b0 = sbias[nrel], b1 = sbias[nrel + 1];
                float v00 = fmaxf(acc[mi][ni][0] + b0, 0.f);
                float v01 = fmaxf(acc[mi][ni][1] + b1, 0.f);
                float v10 = fmaxf(acc[mi][ni][2] + b0, 0.f);
                float v11 = fmaxf(acc[mi][ni][3] + b1, 0.f);
                s[ni][0] += v00 + v10;  s[ni][1] += v01 + v11;
                mx[ni][0] = fmaxf(mx[ni][0], fmaxf(v00, v10));
                mx[ni][1] = fmaxf(mx[ni][1], fmaxf(v01, v11));
            }
#pragma unroll
        for (int o = 4; o < 32; o <<= 1)
#pragma unroll
            for (int ni = 0; ni < 8; ni++)
#pragma unroll
                for (int j = 0; j < 2; j++) {
                    s[ni][j]  += __shfl_xor_sync(0xffffffffu, s[ni][j], o);
                    mx[ni][j]  = fmaxf(mx[ni][j],
                                       __shfl_xor_sync(0xffffffffu, mx[ni][j], o));
                }
        if ((lane >> 2) == 0) {
#pragma unroll
            for (int ni = 0; ni < 8; ni++)
#pragma unroll
                for (int j = 0; j < 2; j++) {
                    int col = wn * 64 + ni * 8 + 2 * lane + j;
                    sSum[wm][col] = s[ni][j];
                    sMax[wm][col] = mx[ni][j];
                }
        }
        __syncthreads();
        {
            float S = sSum[0][tid] + sSum[1][tid];
            float M = fmaxf(sMax[0][tid], sMax[1][tid]);
            atomicAdd(&g_pooled[bIdx * 2 * DH + colBlk + tid], S);
            atomicMax((int*)&g_pooled[bIdx * 2 * DH + DH + colBlk + tid],
                      __float_as_int(M));
        }
    }
}

// ---------------------------------------------------------------------------
// Fused prep kernel: [0,16384) x->fp16 cvt (float4), [16384,16896) zero,
// [16896,17408) W1 transpose, [17408,18432) W2 transpose. 256 threads.
// ---------------------------------------------------------------------------
#define PREP_CVT_BLKS 16384   // MPHI*DIN/4/256
#define PREP_Z_BLKS   512
#define PREP_T1_BLKS  512     // (DH/32)*(DIN/32)
#define PREP_T2_BLKS  1024    // (DH/32)*(DH/32)
#define PREP_BLKS (PREP_CVT_BLKS + PREP_Z_BLKS + PREP_T1_BLKS + PREP_T2_BLKS)

__global__ void __launch_bounds__(256)
prep_kernel(const float* __restrict__ x,
            const float* __restrict__ W1,
            const float* __restrict__ W2)
{
    __shared__ float t[32][33];
    const int b = blockIdx.x;
    const int tid = threadIdx.x;

    if (b < PREP_CVT_BLKS) {
        int i = b * 256 + tid;                     // float4 index
        float4 v = ((const float4*)x)[i];
        uint2 o;
        o.x = pack_h2(v.x, v.y);
        o.y = pack_h2(v.z, v.w);
        ((uint2*)g_x16)[i] = o;
        return;
    }
    if (b < PREP_CVT_BLKS + PREP_Z_BLKS) {
        int i = (b - PREP_CVT_BLKS) * 256 + tid;
        if (i < BB * 2 * DH) g_pooled[i] = 0.f;
        if (i < BB * DH) { g_racc1[i] = 0.f; g_racc2[i] = 0.f; }
        return;
    }
    // transposes: src [R, Cn] fp32 -> dst [Cn, R] fp16
    const float* src;
    unsigned short* dst;
    int R, Cn, bb;
    if (b < PREP_CVT_BLKS + PREP_Z_BLKS + PREP_T1_BLKS) {
        bb = b - (PREP_CVT_BLKS + PREP_Z_BLKS);
        src = W1; dst = g_w1t; R = DIN; Cn = DH;
    } else {
        bb = b - (PREP_CVT_BLKS + PREP_Z_BLKS + PREP_T1_BLKS);
        src = W2; dst = g_w2t; R = DH; Cn = DH;
    }
    const int bx = (bb & 31) * 32;            // column block within Cn (=DH: 32 blocks)
    const int by = (bb >> 5) * 32;            // row block within R
    const int tx = tid & 31, ty = tid >> 5;   // (32, 8)
#pragma unroll
    for (int i = 0; i < 32; i += 8)
        t[ty + i][tx] = src[(size_t)(by + ty + i) * Cn + bx + tx];
    __syncthreads();
#pragma unroll
    for (int i = 0; i < 32; i += 8) {
        int n = bx + ty + i, k = by + tx;
        dst[(size_t)n * R + k] = __half_as_ushort(__float2half_rn(t[tx][ty + i]));
    }
}

// ---------------------------------------------------------------------------
// rho GEMMs: split-K FFMA with atomic fp32 accumulation (KS=128 per split).
// ---------------------------------------------------------------------------
template <int PHASE>
__global__ void __launch_bounds__(256)
rho_partial(const float* __restrict__ W)
{
    const int lda = (PHASE == 0) ? 2 * DH : DH;
    const float* A = (PHASE == 0) ? (const float*)g_pooled : (const float*)g_r1;
    float* acc     = (PHASE == 0) ? g_racc1 : g_racc2;

    __shared__ float As[64][65];
    const int tid = threadIdx.x;
    const int tx = tid & 31, ty = tid >> 5;
    const int col = blockIdx.x * 32 + tx;
    const int k0 = blockIdx.y * 128;

    float a8[8];
#pragma unroll
    for (int r = 0; r < 8; r++) a8[r] = 0.f;

#pragma unroll
    for (int kt = 0; kt < 128; kt += 64) {
#pragma unroll
        for (int l = 0; l < 4; l++) {
            int f = tid + l * 256;
            int row = f >> 4, q = f & 15;
            float4 v = *reinterpret_cast<const float4*>(
                &A[(size_t)row * lda + k0 + kt + q * 4]);
            As[row][q * 4 + 0] = v.x; As[row][q * 4 + 1] = v.y;
            As[row][q * 4 + 2] = v.z; As[row][q * 4 + 3] = v.w;
        }
        __syncthreads();
#pragma unroll
        for (int kk = 0; kk < 64; kk++) {
            float w = W[(size_t)(k0 + kt + kk) * DH + col];
#pragma unroll
            for (int r = 0; r < 8; r++) a8[r] += As[ty * 8 + r][kk] * w;
        }
        __syncthreads();
    }
#pragma unroll
    for (int r = 0; r < 8; r++)
        atomicAdd(&acc[(size_t)(ty * 8 + r) * DH + col], a8[r]);
}

template <int PHASE>
__global__ void bias_relu_kernel(const float* __restrict__ b, float* __restrict__ outp) {
    int i = blockIdx.x * 256 + threadIdx.x;
    const float* acc = (PHASE == 0) ? g_racc1 : g_racc2;
    float* out = (PHASE == 0) ? g_r1 : outp;
    out[i] = fmaxf(acc[i] + b[i & (DH - 1)], 0.f);
}

// ---------------------------------------------------------------------------
// Launch
// ---------------------------------------------------------------------------
extern "C" void kernel_launch(void* const* d_in, const int* in_sizes, int n_in,
                              void* d_out, int out_size)
{
    const float* x   = (const float*)d_in[0];
    const float* W1  = (const float*)d_in[1];
    const float* b1  = (const float*)d_in[2];
    const float* W2  = (const float*)d_in[3];
    const float* b2  = (const float*)d_in[4];
    const float* Wr1 = (const float*)d_in[5];
    const float* br1 = (const float*)d_in[6];
    const float* Wr2 = (const float*)d_in[7];
    const float* br2 = (const float*)d_in[8];
    float* out       = (float*)d_out;

    cudaFuncSetAttribute(phi_gemm<0>, cudaFuncAttributeMaxDynamicSharedMemorySize, DYN_SMEM);
    cudaFuncSetAttribute(phi_gemm<1>, cudaFuncAttributeMaxDynamicSharedMemorySize, DYN_SMEM);

    // fused prep: cvt x, zero accumulators, transpose+cvt W1/W2
    prep_kernel<<<PREP_BLKS, 256>>>(x, W1, W2);

    // phi layer 1: h1 = relu(x @ W1 + b1) -> fp16
    phi_gemm<0><<<dim3(DH / BN, MPHI / BM), 256, DYN_SMEM>>>(b1, DIN, DIN / BK);
    // phi layer 2 + fused sum/max pooling
    phi_gemm<1><<<dim3(DH / BN, MPHI / BM), 256, DYN_SMEM>>>(b2, DH, DH / BK);

    // rho (fp32 exact), KS=128 splits
    rho_partial<0><<<dim3(DH / 32, 16), 256>>>(Wr1);   // K=2048 -> 16 splits
    bias_relu_kernel<0><<<BB * DH / 256, 256>>>(br1, nullptr);
    rho_partial<1><<<dim3(DH / 32, 8), 256>>>(Wr2);    // K=1024 -> 8 splits
    bias_relu_kernel<1><<<BB * DH / 256, 256>>>(br2, out);
}

// round 10
// speedup vs baseline: 6.8392x; 1.0322x over previous
#include <cuda_runtime.h>
#include <cuda_fp16.h>
#include <cstdint>

// ---------------------------------------------------------------------------
// Problem dims
// ---------------------------------------------------------------------------
#define BB   64
#define NSET 512
#define DIN  512
#define DH   1024
#define MPHI (BB * NSET)   // 32768

// GEMM tiling: CTA 128x256, BK=64, warp tile 64x64 (2x4 warps), 4 stages
#define BM 128
#define BN 256
#define BK 64
#define OFFB 16384
#define STG  49152
#define NSTAGE 4
#define DYN_SMEM (NSTAGE * STG + 1024)

// ---------------------------------------------------------------------------
// Device scratch (fp16 words as unsigned short)
// ---------------------------------------------------------------------------
__device__ unsigned short g_x16[(size_t)MPHI * DIN];     // x as fp16
__device__ unsigned short g_w1t[(size_t)DH * DIN];       // W1^T [N,K] fp16
__device__ unsigned short g_w2t[(size_t)DH * DH];        // W2^T [N,K] fp16
__device__ unsigned short g_h1[(size_t)MPHI * DH];       // h1 fp16
__device__ float g_pooled[BB * 2 * DH];
__device__ float g_racc1[BB * DH];
__device__ float g_racc2[BB * DH];

// ---------------------------------------------------------------------------
// PTX helpers
// ---------------------------------------------------------------------------
__device__ __forceinline__ uint32_t smem_u32(const void* p) {
    uint32_t a;
    asm("{ .reg .u64 t; cvta.to.shared.u64 t, %1; cvt.u32.u64 %0, t; }"
        : "=r"(a) : "l"(p));
    return a;
}

__device__ __forceinline__ void cp16(uint32_t dst, const void* src) {
    asm volatile("cp.async.cg.shared.global [%0], [%1], 16;"
                 :: "r"(dst), "l"(src));
}
#define CP_COMMIT() asm volatile("cp.async.commit_group;" ::: "memory")
#define CP_WAIT(n)  asm volatile("cp.async.wait_group %0;" :: "n"(n) : "memory")

__device__ __forceinline__ void ldsm_x4(uint32_t& r0, uint32_t& r1,
                                        uint32_t& r2, uint32_t& r3, uint32_t addr) {
    asm volatile("ldmatrix.sync.aligned.m8n8.x4.shared.b16 {%0,%1,%2,%3}, [%4];"
                 : "=r"(r0), "=r"(r1), "=r"(r2), "=r"(r3) : "r"(addr));
}

__device__ __forceinline__ void mma16816(float* c, const uint32_t* a, const uint32_t* b) {
    asm volatile(
        "mma.sync.aligned.m16n8k16.row.col.f32.f16.f16.f32 "
        "{%0,%1,%2,%3}, {%4,%5,%6,%7}, {%8,%9}, {%0,%1,%2,%3};"
        : "+f"(c[0]), "+f"(c[1]), "+f"(c[2]), "+f"(c[3])
        : "r"(a[0]), "r"(a[1]), "r"(a[2]), "r"(a[3]), "r"(b[0]), "r"(b[1]));
}

__device__ __forceinline__ uint32_t pack_h2(float v0, float v1) {
    __half h0 = __float2half_rn(v0);
    __half h1 = __float2half_rn(v1);
    return ((uint32_t)__half_as_ushort(h1) << 16) | (uint32_t)__half_as_ushort(h0);
}

// ---------------------------------------------------------------------------
// Pure fp16 HMMA GEMM, 4-stage cp.async pipeline (at legacy-HMMA HW floor).
// MODE 0 (layer1): A = x16, B = W1t; epilogue stores h1 fp16.
// MODE 1 (layer2): A = h1,  B = W2t; epilogue fuses sum/max pooling.
// ---------------------------------------------------------------------------
template <int MODE>
__global__ void __launch_bounds__(256, 1)
phi_gemm(const float* __restrict__ bias, int K, int C)
{
    extern __shared__ char dsm[];
    __shared__ float sbias[BN];
    __shared__ float sSum[2][BN], sMax[2][BN];

    const int tid  = threadIdx.x;
    const int lane = tid & 31;
    const int wid  = tid >> 5;
    const int wm   = wid >> 2;     // 0..1
    const int wn   = wid & 3;      // 0..3
    const int rowBlk = blockIdx.y * BM;
    const int colBlk = blockIdx.x * BN;

    const unsigned short* A = (MODE == 0) ? g_x16 : g_h1;
    const unsigned short* Bm = (MODE == 0) ? g_w1t : g_w2t;

    const uint32_t sb = (smem_u32(dsm) + 1023u) & ~1023u;

    if (tid < BN) sbias[tid] = bias[colBlk + tid];

    float acc[4][8][4];
#pragma unroll
    for (int i = 0; i < 4; i++)
#pragma unroll
        for (int j = 0; j < 8; j++)
#pragma unroll
            for (int k = 0; k < 4; k++) acc[i][j][k] = 0.f;

    // ldmatrix per-thread addressing (swizzled 128B rows)
    const int arow = wm * 64 + (lane & 15);
    const uint32_t aRowOff = (uint32_t)arow * 128;
    const uint32_t aXor = ((uint32_t)(arow & 7)) << 4;
    const int brow = wn * 64 + (lane & 15);
    const uint32_t bRowOff = (uint32_t)brow * 128;
    const uint32_t bXor = ((uint32_t)(brow & 7)) << 4;
    const uint32_t csel = ((uint32_t)((lane >> 4) & 1)) << 4;

    auto load_chunk = [&](int stage, int kt) {
        uint32_t st = sb + stage * STG;
#pragma unroll
        for (int l = 0; l < 4; l++) {
            int f = tid + l * 256;
            int r = f >> 3, q = f & 7;
            uint32_t off = (uint32_t)(r * 128) +
                           (((uint32_t)(q * 16)) ^ (((uint32_t)(r & 7)) << 4));
            cp16(st + off, A + (size_t)(rowBlk + r) * K + kt + q * 8);
        }
#pragma unroll
        for (int l = 0; l < 8; l++) {
            int f = tid + l * 256;
            int r = f >> 3, q = f & 7;
            uint32_t off = (uint32_t)(r * 128) +
                           (((uint32_t)(q * 16)) ^ (((uint32_t)(r & 7)) << 4));
            cp16(st + OFFB + off, Bm + (size_t)(colBlk + r) * K + kt + q * 8);
        }
        CP_COMMIT();
    };

    load_chunk(0, 0);
    if (C > 1) load_chunk(1, BK);
    if (C > 2) load_chunk(2, 2 * BK);

    for (int c = 0; c < C; c++) {
        if (c + 2 < C)      { CP_WAIT(2); }
        else if (c + 1 < C) { CP_WAIT(1); }
        else                { CP_WAIT(0); }
        __syncthreads();
        if (c + 3 < C) load_chunk((c + 3) & (NSTAGE - 1), (c + 3) * BK);

        const uint32_t st = sb + (c & (NSTAGE - 1)) * STG;
#pragma unroll
        for (int k16 = 0; k16 < 4; k16++) {
            const uint32_t cb = k16 * 32;
            uint32_t ah[4][4];
#pragma unroll
            for (int mi = 0; mi < 4; mi++) {
                uint32_t aoff = aRowOff + mi * 2048 + ((cb + csel) ^ aXor);
                ldsm_x4(ah[mi][0], ah[mi][1], ah[mi][2], ah[mi][3], st + aoff);
            }
#pragma unroll
            for (int nb = 0; nb < 4; nb++) {
                uint32_t boff = bRowOff + nb * 2048 + ((cb + csel) ^ bXor);
                uint32_t b0, b1, b2, b3;
                ldsm_x4(b0, b1, b2, b3, st + OFFB + boff);
                uint32_t bfr0[2] = {b0, b2};
                uint32_t bfr1[2] = {b1, b3};
#pragma unroll
                for (int mi = 0; mi < 4; mi++) {
                    mma16816(acc[mi][nb * 2],     ah[mi], bfr0);
                    mma16816(acc[mi][nb * 2 + 1], ah[mi], bfr1);
                }
            }
        }
    }

    // ------------------------- epilogue -------------------------
    const int r0base = wm * 64 + (lane >> 2);
    const int n0base = wn * 64 + 2 * (lane & 3);

    if (MODE == 0) {
#pragma unroll
        for (int mi = 0; mi < 4; mi++) {
            int r0 = rowBlk + r0base + mi * 16;
#pragma unroll
            for (int ni = 0; ni < 8; ni++) {
                int nrel = n0base + ni * 8;
                float b0 = sbias[nrel], b1 = sbias[nrel + 1];
                float v00 = fmaxf(acc[mi][ni][0] + b0, 0.f);
                float v01 = fmaxf(acc[mi][ni][1] + b1, 0.f);
                float v10 = fmaxf(acc[mi][ni][2] + b0, 0.f);
                float v11 = fmaxf(acc[mi][ni][3] + b1, 0.f);
                *(uint32_t*)&g_h1[(size_t)r0 * DH + colBlk + nrel] = pack_h2(v00, v01);
                *(uint32_t*)&g_h1[(size_t)(r0 + 8) * DH + colBlk + nrel] = pack_h2(v10, v11);
            }
        }
    } else {
        const int bIdx = rowBlk >> 9;
        float s[8][2], mx[8][2];
#pragma unroll
        for (int ni = 0; ni < 8; ni++) { s[ni][0] = s[ni][1] = 0.f;
                                         mx[ni][0] = mx[ni][1] = 0.f; }
#pragma unroll
        for (int mi = 0; mi < 4; mi++)
#pragma unroll
            for (int ni = 0; ni < 8; ni++) {
                int nrel = n0base + ni * 8;
                float b0 = sbias[nrel], b1 = sbias[nrel + 1];
                float v00 = fmaxf(acc[mi][ni][0] + b0, 0.f);
                float v01 = fmaxf(acc[mi][ni][1] + b1, 0.f);
                float v10 = fmaxf(acc[mi][ni][2] + b0, 0.f);
                float v11 = fmaxf(acc[mi][ni][3] + b1, 0.f);
                s[ni][0] += v00 + v10;  s[ni][1] += v01 + v11;
                mx[ni][0] = fmaxf(mx[ni][0], fmaxf(v00, v10));
                mx[ni][1] = fmaxf(mx[ni][1], fmaxf(v01, v11));
            }
#pragma unroll
        for (int o = 4; o < 32; o <<= 1)
#pragma unroll
            for (int ni = 0; ni < 8; ni++)
#pragma unroll
                for (int j = 0; j < 2; j++) {
                    s[ni][j]  += __shfl_xor_sync(0xffffffffu, s[ni][j], o);
                    mx[ni][j]  = fmaxf(mx[ni][j],
                                       __shfl_xor_sync(0xffffffffu, mx[ni][j], o));
                }
        if ((lane >> 2) == 0) {
#pragma unroll
            for (int ni = 0; ni < 8; ni++)
#pragma unroll
                for (int j = 0; j < 2; j++) {
                    int col = wn * 64 + ni * 8 + 2 * lane + j;
                    sSum[wm][col] = s[ni][j];
                    sMax[wm][col] = mx[ni][j];
                }
        }
        __syncthreads();
        {
            float S = sSum[0][tid] + sSum[1][tid];
            float M = fmaxf(sMax[0][tid], sMax[1][tid]);
            atomicAdd(&g_pooled[bIdx * 2 * DH + colBlk + tid], S);
            atomicMax((int*)&g_pooled[bIdx * 2 * DH + DH + colBlk + tid],
                      __float_as_int(M));
        }
    }
}

// ---------------------------------------------------------------------------
// Fused prep kernel
// ---------------------------------------------------------------------------
#define PREP_CVT_BLKS 16384   // MPHI*DIN/4/256
#define PREP_Z_BLKS   512
#define PREP_T1_BLKS  512     // (DH/32)*(DIN/32)
#define PREP_T2_BLKS  1024    // (DH/32)*(DH/32)
#define PREP_BLKS (PREP_CVT_BLKS + PREP_Z_BLKS + PREP_T1_BLKS + PREP_T2_BLKS)

__global__ void __launch_bounds__(256)
prep_kernel(const float* __restrict__ x,
            const float* __restrict__ W1,
            const float* __restrict__ W2)
{
    __shared__ float t[32][33];
    const int b = blockIdx.x;
    const int tid = threadIdx.x;

    if (b < PREP_CVT_BLKS) {
        int i = b * 256 + tid;                     // float4 index
        float4 v = ((const float4*)x)[i];
        uint2 o;
        o.x = pack_h2(v.x, v.y);
        o.y = pack_h2(v.z, v.w);
        ((uint2*)g_x16)[i] = o;
        return;
    }
    if (b < PREP_CVT_BLKS + PREP_Z_BLKS) {
        int i = (b - PREP_CVT_BLKS) * 256 + tid;
        if (i < BB * 2 * DH) g_pooled[i] = 0.f;
        if (i < BB * DH) { g_racc1[i] = 0.f; g_racc2[i] = 0.f; }
        return;
    }
    const float* src;
    unsigned short* dst;
    int R, Cn, bb;
    if (b < PREP_CVT_BLKS + PREP_Z_BLKS + PREP_T1_BLKS) {
        bb = b - (PREP_CVT_BLKS + PREP_Z_BLKS);
        src = W1; dst = g_w1t; R = DIN; Cn = DH;
    } else {
        bb = b - (PREP_CVT_BLKS + PREP_Z_BLKS + PREP_T1_BLKS);
        src = W2; dst = g_w2t; R = DH; Cn = DH;
    }
    const int bx = (bb & 31) * 32;
    const int by = (bb >> 5) * 32;
    const int tx = tid & 31, ty = tid >> 5;
#pragma unroll
    for (int i = 0; i < 32; i += 8)
        t[ty + i][tx] = src[(size_t)(by + ty + i) * Cn + bx + tx];
    __syncthreads();
#pragma unroll
    for (int i = 0; i < 32; i += 8) {
        int n = bx + ty + i, k = by + tx;
        dst[(size_t)n * R + k] = __half_as_ushort(__float2half_rn(t[tx][ty + i]));
    }
}

// ---------------------------------------------------------------------------
// rho GEMMs: split-K FFMA, 4x4 register blocking, A & W staged in smem.
// Tile: 64 rows (all of M) x 64 cols, KS = 128 per split (2 x 64 inner tiles).
// PHASE 0: A = g_pooled (lda 2048) -> g_racc1.
// PHASE 1: A = relu(g_racc1 + br1) applied on load (lda 1024) -> g_racc2.
// ---------------------------------------------------------------------------
template <int PHASE>
__global__ void __launch_bounds__(256)
rho_partial(const float* __restrict__ W, const float* __restrict__ bias_in)
{
    const int lda = (PHASE == 0) ? 2 * DH : DH;
    const float* A = (PHASE == 0) ? (const float*)g_pooled : (const float*)g_racc1;
    float* acc     = (PHASE == 0) ? g_racc1 : g_racc2;

    __shared__ float As[64][65];   // [kk][row]
    __shared__ float Ws[64][65];   // [kk][col]

    const int tid = threadIdx.x;
    const int tx = tid & 15, ty = tid >> 4;    // 16 x 16
    const int col0 = blockIdx.x * 64;
    const int k0 = blockIdx.y * 128;

    float a16[4][4];
#pragma unroll
    for (int i = 0; i < 4; i++)
#pragma unroll
        for (int j = 0; j < 4; j++) a16[i][j] = 0.f;

#pragma unroll
    for (int kt = 0; kt < 2; kt++) {
        const int kbase = k0 + kt * 64;
        // load A slice [64 rows x 64 k], transposed to As[kk][row]
#pragma unroll
        for (int l = 0; l < 4; l++) {
            int f = tid + l * 256;             // 0..1023 (float4 units)
            int row = f >> 4, kq = f & 15;
            float4 v = *reinterpret_cast<const float4*>(
                &A[(size_t)row * lda + kbase + kq * 4]);
            if (PHASE == 1) {
                float4 bv = *reinterpret_cast<const float4*>(&bias_in[kbase + kq * 4]);
                v.x = fmaxf(v.x + bv.x, 0.f); v.y = fmaxf(v.y + bv.y, 0.f);
                v.z = fmaxf(v.z + bv.z, 0.f); v.w = fmaxf(v.w + bv.w, 0.f);
            }
            As[kq * 4 + 0][row] = v.x; As[kq * 4 + 1][row] = v.y;
            As[kq * 4 + 2][row] = v.z; As[kq * 4 + 3][row] = v.w;
        }
        // load W slice [64 k x 64 cols] to Ws[kk][col]
#pragma unroll
        for (int l = 0; l < 4; l++) {
            int f = tid + l * 256;
            int kk = f >> 4, cq = f & 15;
            float4 v = *reinterpret_cast<const float4*>(
                &W[(size_t)(kbase + kk) * DH + col0 + cq * 4]);
            Ws[kk][cq * 4 + 0] = v.x; Ws[kk][cq * 4 + 1] = v.y;
            Ws[kk][cq * 4 + 2] = v.z; Ws[kk][cq * 4 + 3] = v.w;
        }
        __syncthreads();
#pragma unroll
        for (int kk = 0; kk < 64; kk++) {
            float av[4], wv[4];
#pragma unroll
            for (int i = 0; i < 4; i++) av[i] = As[kk][ty * 4 + i];
#pragma unroll
            for (int j = 0; j < 4; j++) wv[j] = Ws[kk][tx * 4 + j];
#pragma unroll
            for (int i = 0; i < 4; i++)
#pragma unroll
                for (int j = 0; j < 4; j++) a16[i][j] += av[i] * wv[j];
        }
        __syncthreads();
    }
#pragma unroll
    for (int i = 0; i < 4; i++)
#pragma unroll
        for (int j = 0; j < 4; j++)
            atomicAdd(&acc[(size_t)(ty * 4 + i) * DH + col0 + tx * 4 + j], a16[i][j]);
}

// final: out = relu(g_racc2 + br2)
__global__ void bias_relu_final(const float* __restrict__ b, float* __restrict__ out) {
    int i = blockIdx.x * 256 + threadIdx.x;
    out[i] = fmaxf(g_racc2[i] + b[i & (DH - 1)], 0.f);
}

// ---------------------------------------------------------------------------
// Launch
// ---------------------------------------------------------------------------
extern "C" void kernel_launch(void* const* d_in, const int* in_sizes, int n_in,
                              void* d_out, int out_size)
{
    const float* x   = (const float*)d_in[0];
    const float* W1  = (const float*)d_in[1];
    const float* b1  = (const float*)d_in[2];
    const float* W2  = (const float*)d_in[3];
    const float* b2  = (const float*)d_in[4];
    const float* Wr1 = (const float*)d_in[5];
    const float* br1 = (const float*)d_in[6];
    const float* Wr2 = (const float*)d_in[7];
    const float* br2 = (const float*)d_in[8];
    float* out       = (float*)d_out;

    cudaFuncSetAttribute(phi_gemm<0>, cudaFuncAttributeMaxDynamicSharedMemorySize, DYN_SMEM);
    cudaFuncSetAttribute(phi_gemm<1>, cudaFuncAttributeMaxDynamicSharedMemorySize, DYN_SMEM);

    // fused prep: cvt x, zero accumulators, transpose+cvt W1/W2
    prep_kernel<<<PREP_BLKS, 256>>>(x, W1, W2);

    // phi layer 1: h1 = relu(x @ W1 + b1) -> fp16
    phi_gemm<0><<<dim3(DH / BN, MPHI / BM), 256, DYN_SMEM>>>(b1, DIN, DIN / BK);
    // phi layer 2 + fused sum/max pooling
    phi_gemm<1><<<dim3(DH / BN, MPHI / BM), 256, DYN_SMEM>>>(b2, DH, DH / BK);

    // rho (fp32 exact): 64x64 tiles, KS=128 splits
    rho_partial<0><<<dim3(DH / 64, 16), 256>>>(Wr1, nullptr);  // K=2048, 16 splits
    rho_partial<1><<<dim3(DH / 64, 8),  256>>>(Wr2, br1);      // K=1024, 8 splits (relu fused)
    bias_relu_final<<<BB * DH / 256, 256>>>(br2, out);
}

// round 13
// speedup vs baseline: 6.9466x; 1.0157x over previous
#include <cuda_runtime.h>
#include <cuda_fp16.h>
#include <cstdint>

// ---------------------------------------------------------------------------
// Problem dims
// ---------------------------------------------------------------------------
#define BB   64
#define NSET 512
#define DIN  512
#define DH   1024
#define MPHI (BB * NSET)   // 32768

// GEMM tiling: CTA 128x256, BK=64, warp tile 64x64 (2x4 warps), 4 stages
#define BM 128
#define BN 256
#define BK 64
#define OFFB 16384
#define STG  49152
#define NSTAGE 4
#define DYN_SMEM (NSTAGE * STG + 1024)

// ---------------------------------------------------------------------------
// Device scratch (fp16 words as unsigned short)
// ---------------------------------------------------------------------------
__device__ unsigned short g_x16[(size_t)MPHI * DIN];     // x as fp16
__device__ unsigned short g_w1t[(size_t)DH * DIN];       // W1^T [N,K] fp16
__device__ unsigned short g_w2t[(size_t)DH * DH];        // W2^T [N,K] fp16
__device__ unsigned short g_h1[(size_t)MPHI * DH];       // h1 fp16
__device__ float g_pooled[BB * 2 * DH];
__device__ float g_racc1[BB * DH];
__device__ float g_racc2[BB * DH];

// ---------------------------------------------------------------------------
// PTX helpers
// ---------------------------------------------------------------------------
__device__ __forceinline__ uint32_t smem_u32(const void* p) {
    uint32_t a;
    asm("{ .reg .u64 t; cvta.to.shared.u64 t, %1; cvt.u32.u64 %0, t; }"
        : "=r"(a) : "l"(p));
    return a;
}

__device__ __forceinline__ void cp16(uint32_t dst, const void* src) {
    asm volatile("cp.async.cg.shared.global [%0], [%1], 16;"
                 :: "r"(dst), "l"(src));
}
#define CP_COMMIT() asm volatile("cp.async.commit_group;" ::: "memory")
#define CP_WAIT(n)  asm volatile("cp.async.wait_group %0;" :: "n"(n) : "memory")

__device__ __forceinline__ void ldsm_x4(uint32_t& r0, uint32_t& r1,
                                        uint32_t& r2, uint32_t& r3, uint32_t addr) {
    asm volatile("ldmatrix.sync.aligned.m8n8.x4.shared.b16 {%0,%1,%2,%3}, [%4];"
                 : "=r"(r0), "=r"(r1), "=r"(r2), "=r"(r3) : "r"(addr));
}

__device__ __forceinline__ void mma16816(float* c, const uint32_t* a, const uint32_t* b) {
    asm volatile(
        "mma.sync.aligned.m16n8k16.row.col.f32.f16.f16.f32 "
        "{%0,%1,%2,%3}, {%4,%5,%6,%7}, {%8,%9}, {%0,%1,%2,%3};"
        : "+f"(c[0]), "+f"(c[1]), "+f"(c[2]), "+f"(c[3])
        : "r"(a[0]), "r"(a[1]), "r"(a[2]), "r"(a[3]), "r"(b[0]), "r"(b[1]));
}

__device__ __forceinline__ uint32_t pack_h2(float v0, float v1) {
    __half h0 = __float2half_rn(v0);
    __half h1 = __float2half_rn(v1);
    return ((uint32_t)__half_as_ushort(h1) << 16) | (uint32_t)__half_as_ushort(h0);
}

// ---------------------------------------------------------------------------
// Pure fp16 HMMA GEMM, 4-stage cp.async pipeline (at legacy-HMMA HW floor).
// MODE 0 (layer1): A = x16, B = W1t; epilogue stores h1 fp16.
// MODE 1 (layer2): A = h1,  B = W2t; epilogue fuses sum/max pooling.
// (UNCHANGED from round 10 — proven correct and at floor.)
// ---------------------------------------------------------------------------
template <int MODE>
__global__ void __launch_bounds__(256, 1)
phi_gemm(const float* __restrict__ bias, int K, int C)
{
    extern __shared__ char dsm[];
    __shared__ float sbias[BN];
    __shared__ float sSum[2][BN], sMax[2][BN];

    const int tid  = threadIdx.x;
    const int lane = tid & 31;
    const int wid  = tid >> 5;
    const int wm   = wid >> 2;     // 0..1
    const int wn   = wid & 3;      // 0..3
    const int rowBlk = blockIdx.y * BM;
    const int colBlk = blockIdx.x * BN;

    const unsigned short* A = (MODE == 0) ? g_x16 : g_h1;
    const unsigned short* Bm = (MODE == 0) ? g_w1t : g_w2t;

    const uint32_t sb = (smem_u32(dsm) + 1023u) & ~1023u;

    if (tid < BN) sbias[tid] = bias[colBlk + tid];

    float acc[4][8][4];
#pragma unroll
    for (int i = 0; i < 4; i++)
#pragma unroll
        for (int j = 0; j < 8; j++)
#pragma unroll
            for (int k = 0; k < 4; k++) acc[i][j][k] = 0.f;

    // ldmatrix per-thread addressing (swizzled 128B rows)
    const int arow = wm * 64 + (lane & 15);
    const uint32_t aRowOff = (uint32_t)arow * 128;
    const uint32_t aXor = ((uint32_t)(arow & 7)) << 4;
    const int brow = wn * 64 + (lane & 15);
    const uint32_t bRowOff = (uint32_t)brow * 128;
    const uint32_t bXor = ((uint32_t)(brow & 7)) << 4;
    const uint32_t csel = ((uint32_t)((lane >> 4) & 1)) << 4;

    auto load_chunk = [&](int stage, int kt) {
        uint32_t st = sb + stage * STG;
#pragma unroll
        for (int l = 0; l < 4; l++) {
            int f = tid + l * 256;
            int r = f >> 3, q = f & 7;
            uint32_t off = (uint32_t)(r * 128) +
                           (((uint32_t)(q * 16)) ^ (((uint32_t)(r & 7)) << 4));
            cp16(st + off, A + (size_t)(rowBlk + r) * K + kt + q * 8);
        }
#pragma unroll
        for (int l = 0; l < 8; l++) {
            int f = tid + l * 256;
            int r = f >> 3, q = f & 7;
            uint32_t off = (uint32_t)(r * 128) +
                           (((uint32_t)(q * 16)) ^ (((uint32_t)(r & 7)) << 4));
            cp16(st + OFFB + off, Bm + (size_t)(colBlk + r) * K + kt + q * 8);
        }
        CP_COMMIT();
    };

    load_chunk(0, 0);
    if (C > 1) load_chunk(1, BK);
    if (C > 2) load_chunk(2, 2 * BK);

    for (int c = 0; c < C; c++) {
        if (c + 2 < C)      { CP_WAIT(2); }
        else if (c + 1 < C) { CP_WAIT(1); }
        else                { CP_WAIT(0); }
        __syncthreads();
        if (c + 3 < C) load_chunk((c + 3) & (NSTAGE - 1), (c + 3) * BK);

        const uint32_t st = sb + (c & (NSTAGE - 1)) * STG;
#pragma unroll
        for (int k16 = 0; k16 < 4; k16++) {
            const uint32_t cb = k16 * 32;
            uint32_t ah[4][4];
#pragma unroll
            for (int mi = 0; mi < 4; mi++) {
                uint32_t aoff = aRowOff + mi * 2048 + ((cb + csel) ^ aXor);
                ldsm_x4(ah[mi][0], ah[mi][1], ah[mi][2], ah[mi][3], st + aoff);
            }
#pragma unroll
            for (int nb = 0; nb < 4; nb++) {
                uint32_t boff = bRowOff + nb * 2048 + ((cb + csel) ^ bXor);
                uint32_t b0, b1, b2, b3;
                ldsm_x4(b0, b1, b2, b3, st + OFFB + boff);
                uint32_t bfr0[2] = {b0, b2};
                uint32_t bfr1[2] = {b1, b3};
#pragma unroll
                for (int mi = 0; mi < 4; mi++) {
                    mma16816(acc[mi][nb * 2],     ah[mi], bfr0);
                    mma16816(acc[mi][nb * 2 + 1], ah[mi], bfr1);
                }
            }
        }
    }

    // ------------------------- epilogue -------------------------
    const int r0base = wm * 64 + (lane >> 2);
    const int n0base = wn * 64 + 2 * (lane & 3);

    if (MODE == 0) {
#pragma unroll
        for (int mi = 0; mi < 4; mi++) {
            int r0 = rowBlk + r0base + mi * 16;
#pragma unroll
            for (int ni = 0; ni < 8; ni++) {
                int nrel = n0base + ni * 8;
                float b0 = sbias[nrel], b1 = sbias[nrel + 1];
                float v00 = fmaxf(acc[mi][ni][0] + b0, 0.f);
                float v01 = fmaxf(acc[mi][ni][1] + b1, 0.f);
                float v10 = fmaxf(acc[mi][ni][2] + b0, 0.f);
                float v11 = fmaxf(acc[mi][ni][3] + b1, 0.f);
                *(uint32_t*)&g_h1[(size_t)r0 * DH + colBlk + nrel] = pack_h2(v00, v01);
                *(uint32_t*)&g_h1[(size_t)(r0 + 8) * DH + colBlk + nrel] = pack_h2(v10, v11);
            }
        }
    } else {
        const int bIdx = rowBlk >> 9;
        float s[8][2], mx[8][2];
#pragma unroll
        for (int ni = 0; ni < 8; ni++) { s[ni][0] = s[ni][1] = 0.f;
                                         mx[ni][0] = mx[ni][1] = 0.f; }
#pragma unroll
        for (int mi = 0; mi < 4; mi++)
#pragma unroll
            for (int ni = 0; ni < 8; ni++) {
                int nrel = n0base + ni * 8;
                float b0 = sbias[nrel], b1 = sbias[nrel + 1];
                float v00 = fmaxf(acc[mi][ni][0] + b0, 0.f);
                float v01 = fmaxf(acc[mi][ni][1] + b1, 0.f);
                float v10 = fmaxf(acc[mi][ni][2] + b0, 0.f);
                float v11 = fmaxf(acc[mi][ni][3] + b1, 0.f);
                s[ni][0] += v00 + v10;  s[ni][1] += v01 + v11;
                mx[ni][0] = fmaxf(mx[ni][0], fmaxf(v00, v10));
                mx[ni][1] = fmaxf(mx[ni][1], fmaxf(v01, v11));
            }
#pragma unroll
        for (int o = 4; o < 32; o <<= 1)
#pragma unroll
            for (int ni = 0; ni < 8; ni++)
#pragma unroll
                for (int j = 0; j < 2; j++) {
                    s[ni][j]  += __shfl_xor_sync(0xffffffffu, s[ni][j], o);
                    mx[ni][j]  = fmaxf(mx[ni][j],
                                       __shfl_xor_sync(0xffffffffu, mx[ni][j], o));
                }
        if ((lane >> 2) == 0) {
#pragma unroll
            for (int ni = 0; ni < 8; ni++)
#pragma unroll
                for (int j = 0; j < 2; j++) {
                    int col = wn * 64 + ni * 8 + 2 * lane + j;
                    sSum[wm][col] = s[ni][j];
                    sMax[wm][col] = mx[ni][j];
                }
        }
        __syncthreads();
        {
            float S = sSum[0][tid] + sSum[1][tid];
            float M = fmaxf(sMax[0][tid], sMax[1][tid]);
            atomicAdd(&g_pooled[bIdx * 2 * DH + colBlk + tid], S);
            atomicMax((int*)&g_pooled[bIdx * 2 * DH + DH + colBlk + tid],
                      __float_as_int(M));
        }
    }
}

// ---------------------------------------------------------------------------
// Fused prep kernel (cvt at 32B/thread: 8192 cvt blocks)
// ---------------------------------------------------------------------------
#define PREP_CVT_BLKS 8192    // MPHI*DIN/8/256 (2 float4 per thread)
#define PREP_Z_BLKS   512
#define PREP_T1_BLKS  512     // (DH/32)*(DIN/32)
#define PREP_T2_BLKS  1024    // (DH/32)*(DH/32)
#define PREP_BLKS (PREP_CVT_BLKS + PREP_Z_BLKS + PREP_T1_BLKS + PREP_T2_BLKS)

__global__ void __launch_bounds__(256)
prep_kernel(const float* __restrict__ x,
            const float* __restrict__ W1,
            const float* __restrict__ W2)
{
    __shared__ float t[32][33];
    const int b = blockIdx.x;
    const int tid = threadIdx.x;

    if (b < PREP_CVT_BLKS) {
        int i = (b * 256 + tid) * 2;               // float4 index (2 per thread)
#pragma unroll
        for (int u = 0; u < 2; u++) {
            float4 v = ((const float4*)x)[i + u];
            uint2 o;
            o.x = pack_h2(v.x, v.y);
            o.y = pack_h2(v.z, v.w);
            ((uint2*)g_x16)[i + u] = o;
        }
        return;
    }
    if (b < PREP_CVT_BLKS + PREP_Z_BLKS) {
        int i = (b - PREP_CVT_BLKS) * 256 + tid;
        if (i < BB * 2 * DH) g_pooled[i] = 0.f;
        if (i < BB * DH) { g_racc1[i] = 0.f; g_racc2[i] = 0.f; }
        return;
    }
    const float* src;
    unsigned short* dst;
    int R, Cn, bb;
    if (b < PREP_CVT_BLKS + PREP_Z_BLKS + PREP_T1_BLKS) {
        bb = b - (PREP_CVT_BLKS + PREP_Z_BLKS);
        src = W1; dst = g_w1t; R = DIN; Cn = DH;
    } else {
        bb = b - (PREP_CVT_BLKS + PREP_Z_BLKS + PREP_T1_BLKS);
        src = W2; dst = g_w2t; R = DH; Cn = DH;
    }
    const int bx = (bb & 31) * 32;
    const int by = (bb >> 5) * 32;
    const int tx = tid & 31, ty = tid >> 5;
#pragma unroll
    for (int i = 0; i < 32; i += 8)
        t[ty + i][tx] = src[(size_t)(by + ty + i) * Cn + bx + tx];
    __syncthreads();
#pragma unroll
    for (int i = 0; i < 32; i += 8) {
        int n = bx + ty + i, k = by + tx;
        dst[(size_t)n * R + k] = __half_as_ushort(__float2half_rn(t[tx][ty + i]));
    }
}

// ---------------------------------------------------------------------------
// rho GEMMs: split-K FFMA, 4x4 register blocking, 16B-aligned smem rows
// (stride 68 floats = 272B) so the inner loop is 2x LDS.128 + 16 FFMA per kk.
// Tile: 64 rows (all of M) x 64 cols, KS = 128 per split.
// PHASE 0: A = g_pooled (lda 2048) -> g_racc1.
// PHASE 1: A = relu(g_racc1 + br1) on load (lda 1024) -> g_racc2.
// ---------------------------------------------------------------------------
template <int PHASE>
__global__ void __launch_bounds__(256)
rho_partial(const float* __restrict__ W, const float* __restrict__ bias_in)
{
    const int lda = (PHASE == 0) ? 2 * DH : DH;
    const float* A = (PHASE == 0) ? (const float*)g_pooled : (const float*)g_racc1;
    float* acc     = (PHASE == 0) ? g_racc1 : g_racc2;

    __shared__ float As[64][68];   // [kk][row], 272B rows (16B aligned)
    __shared__ float Ws[64][68];   // [kk][col]

    const int tid = threadIdx.x;
    const int tx = tid & 15, ty = tid >> 4;    // 16 x 16
    const int col0 = blockIdx.x * 64;
    const int k0 = blockIdx.y * 128;

    float a16[4][4];
#pragma unroll
    for (int i = 0; i < 4; i++)
#pragma unroll
        for (int j = 0; j < 4; j++) a16[i][j] = 0.f;

#pragma unroll
    for (int kt = 0; kt < 2; kt++) {
        const int kbase = k0 + kt * 64;
        // load A slice [64 rows x 64 k], transposed to As[kk][row]
#pragma unroll
        for (int l = 0; l < 4; l++) {
            int f = tid + l * 256;             // 0..1023 (float4 units)
            int row = f >> 4, kq = f & 15;
            float4 v = *reinterpret_cast<const float4*>(
                &A[(size_t)row * lda + kbase + kq * 4]);
            if (PHASE == 1) {
                float4 bv = *reinterpret_cast<const float4*>(&bias_in[kbase + kq * 4]);
                v.x = fmaxf(v.x + bv.x, 0.f); v.y = fmaxf(v.y + bv.y, 0.f);
                v.z = fmaxf(v.z + bv.z, 0.f); v.w = fmaxf(v.w + bv.w, 0.f);
            }
            As[kq * 4 + 0][row] = v.x; As[kq * 4 + 1][row] = v.y;
            As[kq * 4 + 2][row] = v.z; As[kq * 4 + 3][row] = v.w;
        }
        // load W slice [64 k x 64 cols] to Ws[kk][col]
#pragma unroll
        for (int l = 0; l < 4; l++) {
            int f = tid + l * 256;
            int kk = f >> 4, cq = f & 15;
            float4 v = *reinterpret_cast<const float4*>(
                &W[(size_t)(kbase + kk) * DH + col0 + cq * 4]);
            *reinterpret_cast<float4*>(&Ws[kk][cq * 4]) = v;
        }
        __syncthreads();
#pragma unroll
        for (int kk = 0; kk < 64; kk++) {
            float4 av = *reinterpret_cast<const float4*>(&As[kk][ty * 4]);
            float4 wv = *reinterpret_cast<const float4*>(&Ws[kk][tx * 4]);
            float avr[4] = {av.x, av.y, av.z, av.w};
            float wvr[4] = {wv.x, wv.y, wv.z, wv.w};
#pragma unroll
            for (int i = 0; i < 4; i++)
#pragma unroll
                for (int j = 0; j < 4; j++) a16[i][j] += avr[i] * wvr[j];
        }
        __syncthreads();
    }
#pragma unroll
    for (int i = 0; i < 4; i++)
#pragma unroll
        for (int j = 0; j < 4; j++)
            atomicAdd(&acc[(size_t)(ty * 4 + i) * DH + col0 + tx * 4 + j], a16[i][j]);
}

// final: out = relu(g_racc2 + br2)
__global__ void bias_relu_final(const float* __restrict__ b, float* __restrict__ out) {
    int i = blockIdx.x * 256 + threadIdx.x;
    out[i] = fmaxf(g_racc2[i] + b[i & (DH - 1)], 0.f);
}

// ---------------------------------------------------------------------------
// Launch
// ---------------------------------------------------------------------------
extern "C" void kernel_launch(void* const* d_in, const int* in_sizes, int n_in,
                              void* d_out, int out_size)
{
    const float* x   = (const float*)d_in[0];
    const float* W1  = (const float*)d_in[1];
    const float* b1  = (const float*)d_in[2];
    const float* W2  = (const float*)d_in[3];
    const float* b2  = (const float*)d_in[4];
    const float* Wr1 = (const float*)d_in[5];
    const float* br1 = (const float*)d_in[6];
    const float* Wr2 = (const float*)d_in[7];
    const float* br2 = (const float*)d_in[8];
    float* out       = (float*)d_out;

    cudaFuncSetAttribute(phi_gemm<0>, cudaFuncAttributeMaxDynamicSharedMemorySize, DYN_SMEM);
    cudaFuncSetAttribute(phi_gemm<1>, cudaFuncAttributeMaxDynamicSharedMemorySize, DYN_SMEM);

    // fused prep: cvt x, zero accumulators, transpose+cvt W1/W2
    prep_kernel<<<PREP_BLKS, 256>>>(x, W1, W2);

    // phi layer 1: h1 = relu(x @ W1 + b1) -> fp16
    phi_gemm<0><<<dim3(DH / BN, MPHI / BM), 256, DYN_SMEM>>>(b1, DIN, DIN / BK);
    // phi layer 2 + fused sum/max pooling
    phi_gemm<1><<<dim3(DH / BN, MPHI / BM), 256, DYN_SMEM>>>(b2, DH, DH / BK);

    // rho (fp32 exact): 64x64 tiles, KS=128 splits
    rho_partial<0><<<dim3(DH / 64, 16), 256>>>(Wr1, nullptr);  // K=2048, 16 splits
    rho_partial<1><<<dim3(DH / 64, 8),  256>>>(Wr2, br1);      // K=1024, 8 splits (relu fused)
    bias_relu_final<<<BB * DH / 256, 256>>>(br2, out);
}